// round 1
// baseline (speedup 1.0000x reference)
#include <cuda_runtime.h>
#include <cuda_bf16.h>

// Problem constants
#define BATCH 8
#define SEQ   1024
#define DIM   128
#define HEADS 8
#define DH    16
#define FFDIM 512
#define MROWS (BATCH*SEQ)   // 8192

// Scratch (no dynamic allocation allowed)
__device__ __align__(16) float g_qkv[MROWS * 384];  // [row][0:128 q | 128:256 k | 256:384 v]
__device__ __align__(16) float g_att[MROWS * DIM];
__device__ __align__(16) float g_x1 [MROWS * DIM];
__device__ __align__(16) float g_ff [MROWS * FFDIM];

__device__ __forceinline__ float ex2f(float x) {
    float y; asm("ex2.approx.f32 %0, %1;" : "=f"(y) : "f"(x)); return y;
}
__device__ __forceinline__ float rcpf(float x) {
    float y; asm("rcp.approx.f32 %0, %1;" : "=f"(y) : "f"(x)); return y;
}

// ---------------------------------------------------------------------------
// Tiled SGEMM: C[M,N] = A[M,K] @ B[K,N] with fused epilogues.
// BM=128, BN=64, BK=16, 256 threads, 8x4 microtile per thread.
// EPI: 0 = none
//      1 = relu(acc + bias[n])
//      2 = resid[m,n] + alpha*acc
//      3 = resid[m,n] + alpha*(acc + bias[n])
// All dims here are multiples of tile sizes (M=8192, N in {128,512}, K in {128,512}).
// ---------------------------------------------------------------------------
#define BM 128
#define BN 64
#define BK 16

template <int EPI>
__global__ void __launch_bounds__(256) sgemm_k(
    const float* __restrict__ A, const float* __restrict__ B, float* __restrict__ C,
    int M, int N, int K, int lda, int ldb, int ldc,
    const float* __restrict__ bias,
    const float* __restrict__ resid, int ldr,
    const float* __restrict__ alphap)
{
    __shared__ float As[BK][BM];
    __shared__ float Bs[BK][BN];

    const int tid = threadIdx.x;
    const int tx = tid & 15;        // N dir (16 cols of 4)
    const int ty = tid >> 4;        // M dir (16 rows of 8)
    const int row0 = blockIdx.y * BM;
    const int col0 = blockIdx.x * BN;

    float acc[8][4];
#pragma unroll
    for (int i = 0; i < 8; i++)
#pragma unroll
        for (int j = 0; j < 4; j++) acc[i][j] = 0.f;

    for (int k0 = 0; k0 < K; k0 += BK) {
        // Load A tile 128x16 (store transposed As[k][m])
#pragma unroll
        for (int i = 0; i < 2; i++) {
            int id = tid + i * 256;            // 0..511
            int ar = id >> 2;                  // 0..127
            int ak = (id & 3) * 4;             // 0,4,8,12
            float4 v = *(const float4*)&A[(size_t)(row0 + ar) * lda + k0 + ak];
            As[ak + 0][ar] = v.x;
            As[ak + 1][ar] = v.y;
            As[ak + 2][ar] = v.z;
            As[ak + 3][ar] = v.w;
        }
        // Load B tile 16x64
        {
            int br = tid >> 4;                 // 0..15
            int bc = (tid & 15) * 4;           // 0..60
            *(float4*)&Bs[br][bc] = *(const float4*)&B[(size_t)(k0 + br) * ldb + col0 + bc];
        }
        __syncthreads();

#pragma unroll
        for (int k = 0; k < BK; k++) {
            float a[8];
            float4 a0 = *(const float4*)&As[k][ty * 8];
            float4 a1 = *(const float4*)&As[k][ty * 8 + 4];
            a[0] = a0.x; a[1] = a0.y; a[2] = a0.z; a[3] = a0.w;
            a[4] = a1.x; a[5] = a1.y; a[6] = a1.z; a[7] = a1.w;
            float4 b4 = *(const float4*)&Bs[k][tx * 4];
            float b[4] = { b4.x, b4.y, b4.z, b4.w };
#pragma unroll
            for (int i = 0; i < 8; i++)
#pragma unroll
                for (int j = 0; j < 4; j++)
                    acc[i][j] = fmaf(a[i], b[j], acc[i][j]);
        }
        __syncthreads();
    }

    // Epilogue
    float alpha = 0.f;
    if (EPI == 2 || EPI == 3) alpha = __ldg(alphap);
    float4 bv = make_float4(0.f, 0.f, 0.f, 0.f);
    if (EPI == 1 || EPI == 3) bv = *(const float4*)&bias[col0 + tx * 4];

#pragma unroll
    for (int i = 0; i < 8; i++) {
        int r = row0 + ty * 8 + i;
        int c = col0 + tx * 4;
        float4 o;
        o.x = acc[i][0]; o.y = acc[i][1]; o.z = acc[i][2]; o.w = acc[i][3];
        if (EPI == 1) {
            o.x = fmaxf(o.x + bv.x, 0.f);
            o.y = fmaxf(o.y + bv.y, 0.f);
            o.z = fmaxf(o.z + bv.z, 0.f);
            o.w = fmaxf(o.w + bv.w, 0.f);
        } else if (EPI == 2) {
            float4 rv = *(const float4*)&resid[(size_t)r * ldr + c];
            o.x = fmaf(alpha, o.x, rv.x);
            o.y = fmaf(alpha, o.y, rv.y);
            o.z = fmaf(alpha, o.z, rv.z);
            o.w = fmaf(alpha, o.w, rv.w);
        } else if (EPI == 3) {
            float4 rv = *(const float4*)&resid[(size_t)r * ldr + c];
            o.x = fmaf(alpha, o.x + bv.x, rv.x);
            o.y = fmaf(alpha, o.y + bv.y, rv.y);
            o.z = fmaf(alpha, o.z + bv.z, rv.z);
            o.w = fmaf(alpha, o.w + bv.w, rv.w);
        }
        *(float4*)&C[(size_t)r * ldc + c] = o;
    }
}

// ---------------------------------------------------------------------------
// Fused attention: per block = (query tile of 128, head, batch).
// Thread t owns query row n = qt*128 + t. dh = 16 -> q and acc live in regs.
// Key insight: scores are clipped via 10*tanh(.) so global max <= 10.
// Use fixed max: w = exp(10*tanh(s) - 10) = ex2(-28.8539*rcp(ex2(2.88539*s)+1))
//   (t=exp(2s): tanh=(t-1)/(t+1); 10*((t-1)/(t+1)) - 10 = -20/(t+1))
// 3 MUFU ops, no clamping needed (t=inf -> u=0 -> w=1; t=0 -> u=1 -> w=e^-20).
// ---------------------------------------------------------------------------
__global__ void __launch_bounds__(128) attn_k(
    const float* __restrict__ qkv, const float* __restrict__ e,
    float* __restrict__ att)
{
    __shared__ float4 ks[64][4];
    __shared__ float4 vs[64][4];

    const int qt = blockIdx.x;
    const int h  = blockIdx.y;
    const int b  = blockIdx.z;
    const int tid = threadIdx.x;
    const int n = qt * 128 + tid;

    const size_t qoff = ((size_t)(b * SEQ + n)) * 384 + h * DH;
    const float4* qp = (const float4*)(qkv + qoff);
    const float4 q0 = qp[0], q1 = qp[1], q2 = qp[2], q3 = qp[3];

    float4 a0 = make_float4(0, 0, 0, 0), a1 = a0, a2 = a0, a3 = a0;
    float l = 0.f;

    const float* erow = e + ((size_t)(b * SEQ + n)) * SEQ;

    for (int j = 0; j < 16; j++) {
        __syncthreads();   // protect smem from previous iter's readers
        // Cooperative load: 64 keys x 16 floats for K and V (coalesced in 64B chunks)
#pragma unroll
        for (int i = 0; i < 2; i++) {
            int id = tid + i * 128;
            int key = id >> 2;
            int p = id & 3;
            const size_t base = ((size_t)(b * SEQ + j * 64 + key)) * 384 + 128 + h * DH;
            ks[key][p] = *(const float4*)(qkv + base + p * 4);
            vs[key][p] = *(const float4*)(qkv + base + 128 + p * 4);
        }
        __syncthreads();

        const float4* ev4 = (const float4*)(erow + j * 64);
#pragma unroll 4
        for (int mq = 0; mq < 16; mq++) {
            float4 ev = ev4[mq];
            float evs[4] = { ev.x, ev.y, ev.z, ev.w };
#pragma unroll
            for (int t = 0; t < 4; t++) {
                int m = mq * 4 + t;
                float4 k0 = ks[m][0], k1 = ks[m][1], k2 = ks[m][2], k3 = ks[m][3];
                // 4 independent FMA chains for ILP
                float p0 = fmaf(q0.w, k0.w, fmaf(q0.z, k0.z, fmaf(q0.y, k0.y, q0.x * k0.x)));
                float p1 = fmaf(q1.w, k1.w, fmaf(q1.z, k1.z, fmaf(q1.y, k1.y, q1.x * k1.x)));
                float p2 = fmaf(q2.w, k2.w, fmaf(q2.z, k2.z, fmaf(q2.y, k2.y, q2.x * k2.x)));
                float p3 = fmaf(q3.w, k3.w, fmaf(q3.z, k3.z, fmaf(q3.y, k3.y, q3.x * k3.x)));
                float s = fmaf((p0 + p1) + (p2 + p3), 0.25f, evs[t]);
                // w = exp(10*tanh(s) - 10)
                float texp = ex2f(2.8853901f * s);      // exp(2s)
                float u = rcpf(texp + 1.0f);
                float w = ex2f(-28.8539008f * u);       // exp(-20/(t+1))
                l += w;
                float4 v0 = vs[m][0], v1 = vs[m][1], v2 = vs[m][2], v3 = vs[m][3];
                a0.x = fmaf(w, v0.x, a0.x); a0.y = fmaf(w, v0.y, a0.y);
                a0.z = fmaf(w, v0.z, a0.z); a0.w = fmaf(w, v0.w, a0.w);
                a1.x = fmaf(w, v1.x, a1.x); a1.y = fmaf(w, v1.y, a1.y);
                a1.z = fmaf(w, v1.z, a1.z); a1.w = fmaf(w, v1.w, a1.w);
                a2.x = fmaf(w, v2.x, a2.x); a2.y = fmaf(w, v2.y, a2.y);
                a2.z = fmaf(w, v2.z, a2.z); a2.w = fmaf(w, v2.w, a2.w);
                a3.x = fmaf(w, v3.x, a3.x); a3.y = fmaf(w, v3.y, a3.y);
                a3.z = fmaf(w, v3.z, a3.z); a3.w = fmaf(w, v3.w, a3.w);
            }
        }
    }

    const float inv = 1.0f / l;  // accurate division (cheap, once per row)
    float4* op = (float4*)(att + ((size_t)(b * SEQ + n)) * DIM + h * DH);
    a0.x *= inv; a0.y *= inv; a0.z *= inv; a0.w *= inv;
    a1.x *= inv; a1.y *= inv; a1.z *= inv; a1.w *= inv;
    a2.x *= inv; a2.y *= inv; a2.z *= inv; a2.w *= inv;
    a3.x *= inv; a3.y *= inv; a3.z *= inv; a3.w *= inv;
    op[0] = a0; op[1] = a1; op[2] = a2; op[3] = a3;
}

// ---------------------------------------------------------------------------
// Launch
// ---------------------------------------------------------------------------
extern "C" void kernel_launch(void* const* d_in, const int* in_sizes, int n_in,
                              void* d_out, int out_size)
{
    const float* x  = (const float*)d_in[0];
    const float* e  = (const float*)d_in[1];
    const float* Wq = (const float*)d_in[2];
    const float* Wk = (const float*)d_in[3];
    const float* Wv = (const float*)d_in[4];
    const float* Wo = (const float*)d_in[5];
    const float* W1 = (const float*)d_in[6];
    const float* b1 = (const float*)d_in[7];
    const float* W2 = (const float*)d_in[8];
    const float* b2 = (const float*)d_in[9];
    const float* alpha1 = (const float*)d_in[10];
    const float* alpha2 = (const float*)d_in[11];
    float* out = (float*)d_out;

    float *qkv, *att, *x1, *ff;
    cudaGetSymbolAddress((void**)&qkv, g_qkv);
    cudaGetSymbolAddress((void**)&att, g_att);
    cudaGetSymbolAddress((void**)&x1,  g_x1);
    cudaGetSymbolAddress((void**)&ff,  g_ff);

    const dim3 gQKV(DIM / BN, MROWS / BM);       // (2, 64)
    const dim3 gFF1(FFDIM / BN, MROWS / BM);     // (8, 64)

    // Q, K, V projections into strided qkv buffer
    sgemm_k<0><<<gQKV, 256>>>(x, Wq, qkv + 0,   MROWS, DIM, DIM, DIM, DIM, 384, nullptr, nullptr, 0, nullptr);
    sgemm_k<0><<<gQKV, 256>>>(x, Wk, qkv + 128, MROWS, DIM, DIM, DIM, DIM, 384, nullptr, nullptr, 0, nullptr);
    sgemm_k<0><<<gQKV, 256>>>(x, Wv, qkv + 256, MROWS, DIM, DIM, DIM, DIM, 384, nullptr, nullptr, 0, nullptr);

    // Fused edge-biased clipped-softmax attention
    attn_k<<<dim3(SEQ / 128, HEADS, BATCH), 128>>>(qkv, e, att);

    // x1 = x + alpha1 * (att @ Wo)
    sgemm_k<2><<<gQKV, 256>>>(att, Wo, x1, MROWS, DIM, DIM, DIM, DIM, DIM, nullptr, x, DIM, alpha1);

    // ff = relu(x1 @ W1 + b1)
    sgemm_k<1><<<gFF1, 256>>>(x1, W1, ff, MROWS, FFDIM, DIM, DIM, FFDIM, FFDIM, b1, nullptr, 0, nullptr);

    // out = x1 + alpha2 * (ff @ W2 + b2)
    sgemm_k<3><<<gQKV, 256>>>(ff, W2, out, MROWS, DIM, FFDIM, FFDIM, DIM, DIM, b2, x1, DIM, alpha2);
}

// round 2
// speedup vs baseline: 1.1820x; 1.1820x over previous
#include <cuda_runtime.h>
#include <cuda_bf16.h>
#include <cstdint>

// Problem constants
#define BATCH 8
#define SEQ   1024
#define DIM   128
#define HEADS 8
#define DH    16
#define FFDIM 512
#define MROWS (BATCH*SEQ)   // 8192
#define NSPLIT 4            // attention key-splits

// Scratch (no dynamic allocation allowed)
__device__ __align__(16) float g_qkv [MROWS * 384];           // q|k|v strided rows
__device__ __align__(16) float g_attp[NSPLIT * MROWS * DIM];  // unnormalized partial AV
__device__ __align__(16) float g_lp  [NSPLIT * MROWS * HEADS];// partial softmax denoms
__device__ __align__(16) float g_att [MROWS * DIM];
__device__ __align__(16) float g_x1  [MROWS * DIM];
__device__ __align__(16) float g_ff  [MROWS * FFDIM];

typedef unsigned long long u64;

__device__ __forceinline__ float ex2f(float x) {
    float y; asm("ex2.approx.f32 %0, %1;" : "=f"(y) : "f"(x)); return y;
}
__device__ __forceinline__ float rcpf(float x) {
    float y; asm("rcp.approx.f32 %0, %1;" : "=f"(y) : "f"(x)); return y;
}
// Packed f32x2 ops (Blackwell): one issue slot = 2 fp32 FMAs
__device__ __forceinline__ u64 ffma2(u64 a, u64 b, u64 c) {
    u64 d; asm("fma.rn.f32x2 %0, %1, %2, %3;" : "=l"(d) : "l"(a), "l"(b), "l"(c)); return d;
}
__device__ __forceinline__ u64 fadd2(u64 a, u64 b) {
    u64 d; asm("add.rn.f32x2 %0, %1, %2;" : "=l"(d) : "l"(a), "l"(b)); return d;
}
__device__ __forceinline__ u64 pack2(float lo, float hi) {
    u64 d; unsigned l = __float_as_uint(lo), h = __float_as_uint(hi);
    asm("mov.b64 %0, {%1, %2};" : "=l"(d) : "r"(l), "r"(h)); return d;
}
__device__ __forceinline__ void unpack2(u64 v, float& lo, float& hi) {
    unsigned l, h; asm("mov.b64 {%0, %1}, %2;" : "=r"(l), "=r"(h) : "l"(v));
    lo = __uint_as_float(l); hi = __uint_as_float(h);
}

union F4U { float4 f; u64 u[2]; };

// ---------------------------------------------------------------------------
// Tiled SGEMM with f32x2 microkernel. BM=128, BN=64, BK=16, 256 thr, 8x4/thr.
// EPI: 0 none | 1 relu(acc+bias) | 2 resid+alpha*acc | 3 resid+alpha*(acc+bias)
// ---------------------------------------------------------------------------
#define BM 128
#define BN 64
#define BK 16

template <int EPI>
__global__ void __launch_bounds__(256) sgemm_k(
    const float* __restrict__ A, const float* __restrict__ B, float* __restrict__ C,
    int M, int N, int K, int lda, int ldb, int ldc,
    const float* __restrict__ bias,
    const float* __restrict__ resid, int ldr,
    const float* __restrict__ alphap)
{
    __shared__ float As[BK][BM];
    __shared__ float Bs[BK][BN];

    const int tid = threadIdx.x;
    const int tx = tid & 15;        // N dir (16 cols of 4)
    const int ty = tid >> 4;        // M dir (16 rows of 8)
    const int row0 = blockIdx.y * BM;
    const int col0 = blockIdx.x * BN;

    u64 accp[4][4];                 // [i-pair][j], lanes = rows (2ip, 2ip+1)
#pragma unroll
    for (int ip = 0; ip < 4; ip++)
#pragma unroll
        for (int j = 0; j < 4; j++) accp[ip][j] = 0ull;

    for (int k0 = 0; k0 < K; k0 += BK) {
#pragma unroll
        for (int i = 0; i < 2; i++) {
            int id = tid + i * 256;
            int ar = id >> 2;
            int ak = (id & 3) * 4;
            float4 v = *(const float4*)&A[(size_t)(row0 + ar) * lda + k0 + ak];
            As[ak + 0][ar] = v.x;
            As[ak + 1][ar] = v.y;
            As[ak + 2][ar] = v.z;
            As[ak + 3][ar] = v.w;
        }
        {
            int br = tid >> 4;
            int bc = (tid & 15) * 4;
            *(float4*)&Bs[br][bc] = *(const float4*)&B[(size_t)(k0 + br) * ldb + col0 + bc];
        }
        __syncthreads();

#pragma unroll
        for (int k = 0; k < BK; k++) {
            F4U a0, a1;
            a0.f = *(const float4*)&As[k][ty * 8];
            a1.f = *(const float4*)&As[k][ty * 8 + 4];
            u64 ap[4] = { a0.u[0], a0.u[1], a1.u[0], a1.u[1] };
            float4 b4 = *(const float4*)&Bs[k][tx * 4];
            u64 bp[4] = { pack2(b4.x, b4.x), pack2(b4.y, b4.y),
                          pack2(b4.z, b4.z), pack2(b4.w, b4.w) };
#pragma unroll
            for (int ip = 0; ip < 4; ip++)
#pragma unroll
                for (int j = 0; j < 4; j++)
                    accp[ip][j] = ffma2(ap[ip], bp[j], accp[ip][j]);
        }
        __syncthreads();
    }

    // Epilogue
    float alpha = 0.f;
    if (EPI == 2 || EPI == 3) alpha = __ldg(alphap);
    float4 bv = make_float4(0.f, 0.f, 0.f, 0.f);
    if (EPI == 1 || EPI == 3) bv = *(const float4*)&bias[col0 + tx * 4];

#pragma unroll
    for (int ip = 0; ip < 4; ip++) {
        float lo[4], hi[4];
#pragma unroll
        for (int j = 0; j < 4; j++) unpack2(accp[ip][j], lo[j], hi[j]);
#pragma unroll
        for (int par = 0; par < 2; par++) {
            float* v = par ? hi : lo;
            int r = row0 + ty * 8 + ip * 2 + par;
            int c = col0 + tx * 4;
            float4 o = make_float4(v[0], v[1], v[2], v[3]);
            if (EPI == 1) {
                o.x = fmaxf(o.x + bv.x, 0.f); o.y = fmaxf(o.y + bv.y, 0.f);
                o.z = fmaxf(o.z + bv.z, 0.f); o.w = fmaxf(o.w + bv.w, 0.f);
            } else if (EPI == 2) {
                float4 rv = *(const float4*)&resid[(size_t)r * ldr + c];
                o.x = fmaf(alpha, o.x, rv.x); o.y = fmaf(alpha, o.y, rv.y);
                o.z = fmaf(alpha, o.z, rv.z); o.w = fmaf(alpha, o.w, rv.w);
            } else if (EPI == 3) {
                float4 rv = *(const float4*)&resid[(size_t)r * ldr + c];
                o.x = fmaf(alpha, o.x + bv.x, rv.x); o.y = fmaf(alpha, o.y + bv.y, rv.y);
                o.z = fmaf(alpha, o.z + bv.z, rv.z); o.w = fmaf(alpha, o.w + bv.w, rv.w);
            }
            *(float4*)&C[(size_t)r * ldc + c] = o;
        }
    }
}

// ---------------------------------------------------------------------------
// Fused attention (split-K over keys, NSPLIT partials, NO max bookkeeping).
// Block = (query tile 128, head, batch*split). Thread owns one query row.
// w = exp(10*tanh(s) - 10) = ex2(-28.8539*rcp(ex2(2.88539*s)+1)): fixed max,
// partials combine by simple addition.
// e is staged through smem (coalesced LDG, padded conflict-free LDS).
// ---------------------------------------------------------------------------
__global__ void __launch_bounds__(128) attn_k(
    const float* __restrict__ qkv, const float* __restrict__ e,
    float* __restrict__ attp, float* __restrict__ lp)
{
    __shared__ float es[128][65];   // padded: LDS bank = (tid + m) % 32, conflict-free
    __shared__ float4 ks[64][4];
    __shared__ float4 vs[64][4];

    const int qt = blockIdx.x;
    const int h  = blockIdx.y;
    const int bz = blockIdx.z;
    const int b     = bz >> 2;
    const int split = bz & 3;
    const int tid = threadIdx.x;
    const int n = qt * 128 + tid;

    // q in packed f32x2 registers
    const size_t qoff = ((size_t)(b * SEQ + n)) * 384 + h * DH;
    u64 q2[8];
    {
        const float4* qp = (const float4*)(qkv + qoff);
#pragma unroll
        for (int i = 0; i < 4; i++) {
            F4U t; t.f = qp[i];
            q2[2 * i] = t.u[0]; q2[2 * i + 1] = t.u[1];
        }
    }

    u64 acc[8];
#pragma unroll
    for (int i = 0; i < 8; i++) acc[i] = 0ull;
    float l = 0.f;

    const int kstart = split * (SEQ / NSPLIT);   // 256 keys per split

    for (int jc = 0; jc < (SEQ / NSPLIT) / 64; jc++) {   // 4 chunks of 64 keys
        const int k0 = kstart + jc * 64;
        __syncthreads();
        // Stage K/V tiles (coalesced 64B chunks)
#pragma unroll
        for (int i = 0; i < 2; i++) {
            int id = tid + i * 128;
            int key = id >> 2;
            int p = id & 3;
            const size_t base = ((size_t)(b * SEQ + k0 + key)) * 384 + 128 + h * DH;
            ks[key][p] = *(const float4*)(qkv + base + p * 4);
            vs[key][p] = *(const float4*)(qkv + base + 128 + p * 4);
        }
        // Stage e tile 128 queries x 64 keys (coalesced: 16 lanes per row)
#pragma unroll
        for (int i = 0; i < 16; i++) {
            int fid = tid + i * 128;
            int r = fid >> 4;
            int c = (fid & 15) * 4;
            float4 v = *(const float4*)&e[((size_t)(b * SEQ + qt * 128 + r)) * SEQ + k0 + c];
            es[r][c + 0] = v.x; es[r][c + 1] = v.y;
            es[r][c + 2] = v.z; es[r][c + 3] = v.w;
        }
        __syncthreads();

#pragma unroll 4
        for (int m = 0; m < 64; m++) {
            F4U k0u, k1u, k2u, k3u;
            k0u.f = ks[m][0]; k1u.f = ks[m][1]; k2u.f = ks[m][2]; k3u.f = ks[m][3];
            // 4 independent 2-deep FFMA2 chains
            u64 c0 = ffma2(q2[0], k0u.u[0], 0ull); c0 = ffma2(q2[1], k0u.u[1], c0);
            u64 c1 = ffma2(q2[2], k1u.u[0], 0ull); c1 = ffma2(q2[3], k1u.u[1], c1);
            u64 c2 = ffma2(q2[4], k2u.u[0], 0ull); c2 = ffma2(q2[5], k2u.u[1], c2);
            u64 c3 = ffma2(q2[6], k3u.u[0], 0ull); c3 = ffma2(q2[7], k3u.u[1], c3);
            u64 s01 = fadd2(c0, c1);
            u64 s23 = fadd2(c2, c3);
            u64 st  = fadd2(s01, s23);
            float dl, dh2; unpack2(st, dl, dh2);
            float dot = dl + dh2;

            float ev = es[tid][m];
            float s  = fmaf(dot, 0.25f, ev);
            float t  = ex2f(2.8853901f * s);
            float u  = rcpf(t + 1.0f);
            float w  = ex2f(-28.8539008f * u);
            l += w;

            u64 wp = pack2(w, w);
            F4U v0u, v1u, v2u, v3u;
            v0u.f = vs[m][0]; v1u.f = vs[m][1]; v2u.f = vs[m][2]; v3u.f = vs[m][3];
            acc[0] = ffma2(wp, v0u.u[0], acc[0]);
            acc[1] = ffma2(wp, v0u.u[1], acc[1]);
            acc[2] = ffma2(wp, v1u.u[0], acc[2]);
            acc[3] = ffma2(wp, v1u.u[1], acc[3]);
            acc[4] = ffma2(wp, v2u.u[0], acc[4]);
            acc[5] = ffma2(wp, v2u.u[1], acc[5]);
            acc[6] = ffma2(wp, v3u.u[0], acc[6]);
            acc[7] = ffma2(wp, v3u.u[1], acc[7]);
        }
    }

    // Store unnormalized partial + denom
    float* op = attp + ((size_t)split * MROWS + b * SEQ + n) * DIM + h * DH;
#pragma unroll
    for (int i = 0; i < 4; i++) {
        F4U o; o.u[0] = acc[2 * i]; o.u[1] = acc[2 * i + 1];
        *(float4*)(op + 4 * i) = o.f;
    }
    lp[((size_t)split * MROWS + b * SEQ + n) * HEADS + h] = l;
}

// ---------------------------------------------------------------------------
// Combine split partials: att = (sum_s a_s) / (sum_s l_s)
// ---------------------------------------------------------------------------
__global__ void __launch_bounds__(256) combine_k(
    const float* __restrict__ attp, const float* __restrict__ lp,
    float* __restrict__ att)
{
    int idx = blockIdx.x * 256 + threadIdx.x;   // over MROWS*DIM/4
    int row = idx >> 5;                          // 32 float4 per row
    int c4  = idx & 31;
    int h   = c4 >> 2;                           // 4 float4 per head
    float4 s = make_float4(0.f, 0.f, 0.f, 0.f);
    float l = 0.f;
#pragma unroll
    for (int sp = 0; sp < NSPLIT; sp++) {
        float4 v = *(const float4*)&attp[((size_t)sp * MROWS + row) * DIM + c4 * 4];
        s.x += v.x; s.y += v.y; s.z += v.z; s.w += v.w;
        l += lp[((size_t)sp * MROWS + row) * HEADS + h];
    }
    float inv = 1.0f / l;
    s.x *= inv; s.y *= inv; s.z *= inv; s.w *= inv;
    *(float4*)&att[(size_t)row * DIM + c4 * 4] = s;
}

// ---------------------------------------------------------------------------
// Launch
// ---------------------------------------------------------------------------
extern "C" void kernel_launch(void* const* d_in, const int* in_sizes, int n_in,
                              void* d_out, int out_size)
{
    const float* x  = (const float*)d_in[0];
    const float* e  = (const float*)d_in[1];
    const float* Wq = (const float*)d_in[2];
    const float* Wk = (const float*)d_in[3];
    const float* Wv = (const float*)d_in[4];
    const float* Wo = (const float*)d_in[5];
    const float* W1 = (const float*)d_in[6];
    const float* b1 = (const float*)d_in[7];
    const float* W2 = (const float*)d_in[8];
    const float* b2 = (const float*)d_in[9];
    const float* alpha1 = (const float*)d_in[10];
    const float* alpha2 = (const float*)d_in[11];
    float* out = (float*)d_out;

    float *qkv, *attp, *lpv, *att, *x1, *ff;
    cudaGetSymbolAddress((void**)&qkv,  g_qkv);
    cudaGetSymbolAddress((void**)&attp, g_attp);
    cudaGetSymbolAddress((void**)&lpv,  g_lp);
    cudaGetSymbolAddress((void**)&att,  g_att);
    cudaGetSymbolAddress((void**)&x1,   g_x1);
    cudaGetSymbolAddress((void**)&ff,   g_ff);

    const dim3 gQKV(DIM / BN, MROWS / BM);       // (2, 64)
    const dim3 gFF1(FFDIM / BN, MROWS / BM);     // (8, 64)

    sgemm_k<0><<<gQKV, 256>>>(x, Wq, qkv + 0,   MROWS, DIM, DIM, DIM, DIM, 384, nullptr, nullptr, 0, nullptr);
    sgemm_k<0><<<gQKV, 256>>>(x, Wk, qkv + 128, MROWS, DIM, DIM, DIM, DIM, 384, nullptr, nullptr, 0, nullptr);
    sgemm_k<0><<<gQKV, 256>>>(x, Wv, qkv + 256, MROWS, DIM, DIM, DIM, DIM, 384, nullptr, nullptr, 0, nullptr);

    attn_k<<<dim3(SEQ / 128, HEADS, BATCH * NSPLIT), 128>>>(qkv, e, attp, lpv);
    combine_k<<<(MROWS * DIM / 4) / 256, 256>>>(attp, lpv, att);

    sgemm_k<2><<<gQKV, 256>>>(att, Wo, x1, MROWS, DIM, DIM, DIM, DIM, DIM, nullptr, x, DIM, alpha1);
    sgemm_k<1><<<gFF1, 256>>>(x1, W1, ff, MROWS, FFDIM, DIM, DIM, FFDIM, FFDIM, b1, nullptr, 0, nullptr);
    sgemm_k<3><<<gQKV, 256>>>(ff, W2, out, MROWS, DIM, FFDIM, FFDIM, DIM, DIM, b2, x1, DIM, alpha2);
}

// round 3
// speedup vs baseline: 1.3203x; 1.1170x over previous
#include <cuda_runtime.h>
#include <cuda_bf16.h>
#include <cstdint>

// Problem constants
#define BATCH 8
#define SEQ   1024
#define DIM   128
#define HEADS 8
#define DH    16
#define FFDIM 512
#define MROWS (BATCH*SEQ)   // 8192
#define NSPLIT 4            // attention key-splits
#define QTILE 256           // queries per attention block (2 per thread)
#define KCHUNK 32           // keys staged per chunk

// Scratch (no dynamic allocation allowed)
__device__ __align__(16) float g_qkv [MROWS * 384];
__device__ __align__(16) float g_attp[NSPLIT * MROWS * DIM];
__device__ __align__(16) float g_lp  [NSPLIT * MROWS * HEADS];
__device__ __align__(16) float g_att [MROWS * DIM];
__device__ __align__(16) float g_x1  [MROWS * DIM];
__device__ __align__(16) float g_ff  [MROWS * FFDIM];

typedef unsigned long long u64;

__device__ __forceinline__ float ex2f(float x) {
    float y; asm("ex2.approx.f32 %0, %1;" : "=f"(y) : "f"(x)); return y;
}
__device__ __forceinline__ float rcpf(float x) {
    float y; asm("rcp.approx.f32 %0, %1;" : "=f"(y) : "f"(x)); return y;
}
__device__ __forceinline__ u64 ffma2(u64 a, u64 b, u64 c) {
    u64 d; asm("fma.rn.f32x2 %0, %1, %2, %3;" : "=l"(d) : "l"(a), "l"(b), "l"(c)); return d;
}
__device__ __forceinline__ u64 fadd2(u64 a, u64 b) {
    u64 d; asm("add.rn.f32x2 %0, %1, %2;" : "=l"(d) : "l"(a), "l"(b)); return d;
}
__device__ __forceinline__ u64 pack2(float lo, float hi) {
    u64 d; unsigned l = __float_as_uint(lo), h = __float_as_uint(hi);
    asm("mov.b64 %0, {%1, %2};" : "=l"(d) : "r"(l), "r"(h)); return d;
}
__device__ __forceinline__ void unpack2(u64 v, float& lo, float& hi) {
    unsigned l, h; asm("mov.b64 {%0, %1}, %2;" : "=r"(l), "=r"(h) : "l"(v));
    lo = __uint_as_float(l); hi = __uint_as_float(h);
}

union F4U { float4 f; u64 u[2]; };

// ---------------------------------------------------------------------------
// Tiled SGEMM, f32x2 microkernel, BK=32, register prefetch of next tile.
// BM=128, BN=64, 256 threads, 8x4 microtile.
// EPI: 0 none | 1 relu(acc+bias) | 2 resid+alpha*acc | 3 resid+alpha*(acc+bias)
// ---------------------------------------------------------------------------
#define BM 128
#define BN 64
#define BK 32

template <int EPI>
__global__ void __launch_bounds__(256) sgemm_k(
    const float* __restrict__ A, const float* __restrict__ B, float* __restrict__ C,
    int M, int N, int K, int lda, int ldb, int ldc,
    const float* __restrict__ bias,
    const float* __restrict__ resid, int ldr,
    const float* __restrict__ alphap)
{
    __shared__ float As[BK][BM];
    __shared__ float Bs[BK][BN];

    const int tid = threadIdx.x;
    const int tx = tid & 15;
    const int ty = tid >> 4;
    const int row0 = blockIdx.y * BM;
    const int col0 = blockIdx.x * BN;

    // A-load mapping: id -> (ar, ak)
    const int a_ar = tid >> 3;            // +32 per i
    const int a_ak = (tid & 7) * 4;
    // B-load mapping
    const int b_br = tid >> 4;            // +16 per i
    const int b_bc = (tid & 15) * 4;

    u64 accp[4][4];
#pragma unroll
    for (int ip = 0; ip < 4; ip++)
#pragma unroll
        for (int j = 0; j < 4; j++) accp[ip][j] = 0ull;

    float4 Ar[4], Br[2];
    // prologue: load tile 0
#pragma unroll
    for (int i = 0; i < 4; i++)
        Ar[i] = *(const float4*)&A[(size_t)(row0 + a_ar + i * 32) * lda + a_ak];
#pragma unroll
    for (int i = 0; i < 2; i++)
        Br[i] = *(const float4*)&B[(size_t)(b_br + i * 16) * ldb + col0 + b_bc];

    const int nk = K / BK;
    for (int kt = 0; kt < nk; kt++) {
        // stage current tile
#pragma unroll
        for (int i = 0; i < 4; i++) {
            As[a_ak + 0][a_ar + i * 32] = Ar[i].x;
            As[a_ak + 1][a_ar + i * 32] = Ar[i].y;
            As[a_ak + 2][a_ar + i * 32] = Ar[i].z;
            As[a_ak + 3][a_ar + i * 32] = Ar[i].w;
        }
#pragma unroll
        for (int i = 0; i < 2; i++)
            *(float4*)&Bs[b_br + i * 16][b_bc] = Br[i];
        __syncthreads();

        // prefetch next tile into regs (overlaps with compute below)
        if (kt + 1 < nk) {
            const int k0 = (kt + 1) * BK;
#pragma unroll
            for (int i = 0; i < 4; i++)
                Ar[i] = *(const float4*)&A[(size_t)(row0 + a_ar + i * 32) * lda + k0 + a_ak];
#pragma unroll
            for (int i = 0; i < 2; i++)
                Br[i] = *(const float4*)&B[(size_t)(k0 + b_br + i * 16) * ldb + col0 + b_bc];
        }

#pragma unroll 8
        for (int k = 0; k < BK; k++) {
            F4U a0, a1;
            a0.f = *(const float4*)&As[k][ty * 8];
            a1.f = *(const float4*)&As[k][ty * 8 + 4];
            u64 ap[4] = { a0.u[0], a0.u[1], a1.u[0], a1.u[1] };
            float4 b4 = *(const float4*)&Bs[k][tx * 4];
            u64 bp[4] = { pack2(b4.x, b4.x), pack2(b4.y, b4.y),
                          pack2(b4.z, b4.z), pack2(b4.w, b4.w) };
#pragma unroll
            for (int ip = 0; ip < 4; ip++)
#pragma unroll
                for (int j = 0; j < 4; j++)
                    accp[ip][j] = ffma2(ap[ip], bp[j], accp[ip][j]);
        }
        __syncthreads();
    }

    float alpha = 0.f;
    if (EPI == 2 || EPI == 3) alpha = __ldg(alphap);
    float4 bv = make_float4(0.f, 0.f, 0.f, 0.f);
    if (EPI == 1 || EPI == 3) bv = *(const float4*)&bias[col0 + tx * 4];

#pragma unroll
    for (int ip = 0; ip < 4; ip++) {
        float lo[4], hi[4];
#pragma unroll
        for (int j = 0; j < 4; j++) unpack2(accp[ip][j], lo[j], hi[j]);
#pragma unroll
        for (int par = 0; par < 2; par++) {
            float* v = par ? hi : lo;
            int r = row0 + ty * 8 + ip * 2 + par;
            int c = col0 + tx * 4;
            float4 o = make_float4(v[0], v[1], v[2], v[3]);
            if (EPI == 1) {
                o.x = fmaxf(o.x + bv.x, 0.f); o.y = fmaxf(o.y + bv.y, 0.f);
                o.z = fmaxf(o.z + bv.z, 0.f); o.w = fmaxf(o.w + bv.w, 0.f);
            } else if (EPI == 2) {
                float4 rv = *(const float4*)&resid[(size_t)r * ldr + c];
                o.x = fmaf(alpha, o.x, rv.x); o.y = fmaf(alpha, o.y, rv.y);
                o.z = fmaf(alpha, o.z, rv.z); o.w = fmaf(alpha, o.w, rv.w);
            } else if (EPI == 3) {
                float4 rv = *(const float4*)&resid[(size_t)r * ldr + c];
                o.x = fmaf(alpha, o.x + bv.x, rv.x); o.y = fmaf(alpha, o.y + bv.y, rv.y);
                o.z = fmaf(alpha, o.z + bv.z, rv.z); o.w = fmaf(alpha, o.w + bv.w, rv.w);
            }
            *(float4*)&C[(size_t)r * ldc + c] = o;
        }
    }
}

// ---------------------------------------------------------------------------
// Fused attention, split-K, 2 queries per thread (amortizes K/V broadcast LDS).
// Block = 128 threads, 256-query tile; thread owns rows (tid) and (tid+128).
// w = exp(10*tanh(s)-10): fixed max (clip bound), partials sum directly.
// ---------------------------------------------------------------------------
__global__ void __launch_bounds__(128) attn_k(
    const float* __restrict__ qkv, const float* __restrict__ e,
    float* __restrict__ attp, float* __restrict__ lp)
{
    __shared__ float  es[QTILE][33];        // [query][key], stride 33: conflict-free
    __shared__ float4 kvs[KCHUNK][8];       // [key][0:4 K | 4:8 V]

    const int qt = blockIdx.x;              // 0..SEQ/QTILE-1
    const int h  = blockIdx.y;
    const int bz = blockIdx.z;
    const int b     = bz >> 2;
    const int split = bz & 3;
    const int tid = threadIdx.x;
    const int na = qt * QTILE + tid;        // query A
    const int nb = na + 128;                // query B

    u64 q2a[8], q2b[8];
    {
        const float4* qpa = (const float4*)(qkv + ((size_t)(b * SEQ + na)) * 384 + h * DH);
        const float4* qpb = (const float4*)(qkv + ((size_t)(b * SEQ + nb)) * 384 + h * DH);
#pragma unroll
        for (int i = 0; i < 4; i++) {
            F4U t; t.f = qpa[i]; q2a[2 * i] = t.u[0]; q2a[2 * i + 1] = t.u[1];
            F4U s; s.f = qpb[i]; q2b[2 * i] = s.u[0]; q2b[2 * i + 1] = s.u[1];
        }
    }

    u64 acca[8], accb[8];
#pragma unroll
    for (int i = 0; i < 8; i++) { acca[i] = 0ull; accb[i] = 0ull; }
    float la = 0.f, lb = 0.f;

    const int kstart = split * (SEQ / NSPLIT);      // 256 keys/split

    for (int jc = 0; jc < (SEQ / NSPLIT) / KCHUNK; jc++) {   // 8 chunks of 32
        const int k0 = kstart + jc * KCHUNK;
        __syncthreads();
        // K/V tile: 32 keys x 8 float4 = 256 loads, 128 thr -> 2 each
#pragma unroll
        for (int i = 0; i < 2; i++) {
            int id = tid + i * 128;
            int key = id >> 3;
            int p = id & 7;
            const size_t base = ((size_t)(b * SEQ + k0 + key)) * 384 + 128 + h * DH
                              + (p & 3) * 4 + (p >> 2) * 128;
            kvs[key][p] = *(const float4*)(qkv + base);
        }
        // e tile: 256 q x 32 k = 2048 float4-loads? (8192 floats = 2048 f4), 16 per thread
#pragma unroll
        for (int i = 0; i < 16; i++) {
            int fid = tid + i * 128;        // 0..2047
            int k4 = fid & 7;               // float4 col
            int q  = fid >> 3;              // 0..255
            float4 v = *(const float4*)&e[((size_t)(b * SEQ + qt * QTILE + q)) * SEQ + k0 + k4 * 4];
            es[q][k4 * 4 + 0] = v.x; es[q][k4 * 4 + 1] = v.y;
            es[q][k4 * 4 + 2] = v.z; es[q][k4 * 4 + 3] = v.w;
        }
        __syncthreads();

#pragma unroll 4
        for (int m = 0; m < KCHUNK; m++) {
            F4U kk0, kk1, kk2, kk3;
            kk0.f = kvs[m][0]; kk1.f = kvs[m][1]; kk2.f = kvs[m][2]; kk3.f = kvs[m][3];
            // QK dots, 2 queries, interleaved for ILP
            u64 ca0 = ffma2(q2a[0], kk0.u[0], 0ull);
            u64 cb0 = ffma2(q2b[0], kk0.u[0], 0ull);
            u64 ca1 = ffma2(q2a[2], kk1.u[0], 0ull);
            u64 cb1 = ffma2(q2b[2], kk1.u[0], 0ull);
            u64 ca2 = ffma2(q2a[4], kk2.u[0], 0ull);
            u64 cb2 = ffma2(q2b[4], kk2.u[0], 0ull);
            u64 ca3 = ffma2(q2a[6], kk3.u[0], 0ull);
            u64 cb3 = ffma2(q2b[6], kk3.u[0], 0ull);
            ca0 = ffma2(q2a[1], kk0.u[1], ca0);
            cb0 = ffma2(q2b[1], kk0.u[1], cb0);
            ca1 = ffma2(q2a[3], kk1.u[1], ca1);
            cb1 = ffma2(q2b[3], kk1.u[1], cb1);
            ca2 = ffma2(q2a[5], kk2.u[1], ca2);
            cb2 = ffma2(q2b[5], kk2.u[1], cb2);
            ca3 = ffma2(q2a[7], kk3.u[1], ca3);
            cb3 = ffma2(q2b[7], kk3.u[1], cb3);
            u64 sa = fadd2(fadd2(ca0, ca1), fadd2(ca2, ca3));
            u64 sb = fadd2(fadd2(cb0, cb1), fadd2(cb2, cb3));
            float sal, sah, sbl, sbh;
            unpack2(sa, sal, sah);
            unpack2(sb, sbl, sbh);
            float dota = sal + sah;
            float dotb = sbl + sbh;

            float eva = es[tid][m];
            float evb = es[tid + 128][m];
            float ssa = fmaf(dota, 0.25f, eva);
            float ssb = fmaf(dotb, 0.25f, evb);
            float ta = ex2f(2.8853901f * ssa);
            float tb = ex2f(2.8853901f * ssb);
            float ua = rcpf(ta + 1.0f);
            float ub = rcpf(tb + 1.0f);
            float wa = ex2f(-28.8539008f * ua);
            float wb = ex2f(-28.8539008f * ub);
            la += wa; lb += wb;

            u64 wpa = pack2(wa, wa);
            u64 wpb = pack2(wb, wb);
            F4U vv0, vv1, vv2, vv3;
            vv0.f = kvs[m][4]; vv1.f = kvs[m][5]; vv2.f = kvs[m][6]; vv3.f = kvs[m][7];
            acca[0] = ffma2(wpa, vv0.u[0], acca[0]);
            accb[0] = ffma2(wpb, vv0.u[0], accb[0]);
            acca[1] = ffma2(wpa, vv0.u[1], acca[1]);
            accb[1] = ffma2(wpb, vv0.u[1], accb[1]);
            acca[2] = ffma2(wpa, vv1.u[0], acca[2]);
            accb[2] = ffma2(wpb, vv1.u[0], accb[2]);
            acca[3] = ffma2(wpa, vv1.u[1], acca[3]);
            accb[3] = ffma2(wpb, vv1.u[1], accb[3]);
            acca[4] = ffma2(wpa, vv2.u[0], acca[4]);
            accb[4] = ffma2(wpb, vv2.u[0], accb[4]);
            acca[5] = ffma2(wpa, vv2.u[1], acca[5]);
            accb[5] = ffma2(wpb, vv2.u[1], accb[5]);
            acca[6] = ffma2(wpa, vv3.u[0], acca[6]);
            accb[6] = ffma2(wpb, vv3.u[0], accb[6]);
            acca[7] = ffma2(wpa, vv3.u[1], acca[7]);
            accb[7] = ffma2(wpb, vv3.u[1], accb[7]);
        }
    }

    // Store unnormalized partials + denoms
    float* opa = attp + ((size_t)split * MROWS + b * SEQ + na) * DIM + h * DH;
    float* opb = attp + ((size_t)split * MROWS + b * SEQ + nb) * DIM + h * DH;
#pragma unroll
    for (int i = 0; i < 4; i++) {
        F4U oa; oa.u[0] = acca[2 * i]; oa.u[1] = acca[2 * i + 1];
        *(float4*)(opa + 4 * i) = oa.f;
        F4U ob; ob.u[0] = accb[2 * i]; ob.u[1] = accb[2 * i + 1];
        *(float4*)(opb + 4 * i) = ob.f;
    }
    lp[((size_t)split * MROWS + b * SEQ + na) * HEADS + h] = la;
    lp[((size_t)split * MROWS + b * SEQ + nb) * HEADS + h] = lb;
}

// ---------------------------------------------------------------------------
// Combine split partials: att = (sum_s a_s) / (sum_s l_s)
// ---------------------------------------------------------------------------
__global__ void __launch_bounds__(256) combine_k(
    const float* __restrict__ attp, const float* __restrict__ lp,
    float* __restrict__ att)
{
    int idx = blockIdx.x * 256 + threadIdx.x;
    int row = idx >> 5;
    int c4  = idx & 31;
    int h   = c4 >> 2;
    float4 s = make_float4(0.f, 0.f, 0.f, 0.f);
    float l = 0.f;
#pragma unroll
    for (int sp = 0; sp < NSPLIT; sp++) {
        float4 v = *(const float4*)&attp[((size_t)sp * MROWS + row) * DIM + c4 * 4];
        s.x += v.x; s.y += v.y; s.z += v.z; s.w += v.w;
        l += lp[((size_t)sp * MROWS + row) * HEADS + h];
    }
    float inv = 1.0f / l;
    s.x *= inv; s.y *= inv; s.z *= inv; s.w *= inv;
    *(float4*)&att[(size_t)row * DIM + c4 * 4] = s;
}

// ---------------------------------------------------------------------------
// Launch
// ---------------------------------------------------------------------------
extern "C" void kernel_launch(void* const* d_in, const int* in_sizes, int n_in,
                              void* d_out, int out_size)
{
    const float* x  = (const float*)d_in[0];
    const float* e  = (const float*)d_in[1];
    const float* Wq = (const float*)d_in[2];
    const float* Wk = (const float*)d_in[3];
    const float* Wv = (const float*)d_in[4];
    const float* Wo = (const float*)d_in[5];
    const float* W1 = (const float*)d_in[6];
    const float* b1 = (const float*)d_in[7];
    const float* W2 = (const float*)d_in[8];
    const float* b2 = (const float*)d_in[9];
    const float* alpha1 = (const float*)d_in[10];
    const float* alpha2 = (const float*)d_in[11];
    float* out = (float*)d_out;

    float *qkv, *attp, *lpv, *att, *x1, *ff;
    cudaGetSymbolAddress((void**)&qkv,  g_qkv);
    cudaGetSymbolAddress((void**)&attp, g_attp);
    cudaGetSymbolAddress((void**)&lpv,  g_lp);
    cudaGetSymbolAddress((void**)&att,  g_att);
    cudaGetSymbolAddress((void**)&x1,   g_x1);
    cudaGetSymbolAddress((void**)&ff,   g_ff);

    const dim3 gQKV(DIM / BN, MROWS / BM);       // (2, 64)
    const dim3 gFF1(FFDIM / BN, MROWS / BM);     // (8, 64)

    sgemm_k<0><<<gQKV, 256>>>(x, Wq, qkv + 0,   MROWS, DIM, DIM, DIM, DIM, 384, nullptr, nullptr, 0, nullptr);
    sgemm_k<0><<<gQKV, 256>>>(x, Wk, qkv + 128, MROWS, DIM, DIM, DIM, DIM, 384, nullptr, nullptr, 0, nullptr);
    sgemm_k<0><<<gQKV, 256>>>(x, Wv, qkv + 256, MROWS, DIM, DIM, DIM, DIM, 384, nullptr, nullptr, 0, nullptr);

    attn_k<<<dim3(SEQ / QTILE, HEADS, BATCH * NSPLIT), 128>>>(qkv, e, attp, lpv);
    combine_k<<<(MROWS * DIM / 4) / 256, 256>>>(attp, lpv, att);

    sgemm_k<2><<<gQKV, 256>>>(att, Wo, x1, MROWS, DIM, DIM, DIM, DIM, DIM, nullptr, x, DIM, alpha1);
    sgemm_k<1><<<gFF1, 256>>>(x1, W1, ff, MROWS, FFDIM, DIM, DIM, FFDIM, FFDIM, b1, nullptr, 0, nullptr);
    sgemm_k<3><<<gQKV, 256>>>(ff, W2, out, MROWS, DIM, FFDIM, FFDIM, DIM, DIM, b2, x1, DIM, alpha2);
}

// round 5
// speedup vs baseline: 1.4015x; 1.0615x over previous
#include <cuda_runtime.h>
#include <cuda_bf16.h>
#include <cstdint>

// Problem constants
#define BATCH 8
#define SEQ   1024
#define DIM   128
#define HEADS 8
#define DH    16
#define FFDIM 512
#define MROWS (BATCH*SEQ)   // 8192
#define NSPLIT 4
#define QTILE 256
#define KCHUNK 32

typedef unsigned long long u64;
typedef unsigned int u32;
typedef unsigned short u16;

// ------------------------- scratch (static only) ---------------------------
__device__ __align__(16) float g_qkv [MROWS * 384];            // fp32 q|k|v
__device__ __align__(16) float g_attp[NSPLIT * MROWS * DIM];
__device__ __align__(16) float g_lp  [NSPLIT * MROWS * HEADS];
__device__ __align__(16) float g_x1  [MROWS * DIM];            // fp32 (resid for ff2)
// bf16 hi/lo split operands
__device__ __align__(16) __nv_bfloat16 g_xh [MROWS * DIM],  g_xl [MROWS * DIM];
__device__ __align__(16) __nv_bfloat16 g_ath[MROWS * DIM],  g_atl[MROWS * DIM];
__device__ __align__(16) __nv_bfloat16 g_x1h[MROWS * DIM],  g_x1l[MROWS * DIM];
__device__ __align__(16) __nv_bfloat16 g_ffh[MROWS * FFDIM],g_ffl[MROWS * FFDIM];
// transposed + split weights: [N x K] K-major
__device__ __align__(16) __nv_bfloat16 g_WqkvTh[384 * DIM], g_WqkvTl[384 * DIM];
__device__ __align__(16) __nv_bfloat16 g_WoTh [DIM * DIM],  g_WoTl [DIM * DIM];
__device__ __align__(16) __nv_bfloat16 g_W1Th [FFDIM * DIM],g_W1Tl [FFDIM * DIM];
__device__ __align__(16) __nv_bfloat16 g_W2Th [DIM * FFDIM],g_W2Tl [DIM * FFDIM];

// ------------------------------ helpers ------------------------------------
__device__ __forceinline__ float ex2f(float x) {
    float y; asm("ex2.approx.f32 %0, %1;" : "=f"(y) : "f"(x)); return y;
}
__device__ __forceinline__ float rcpf(float x) {
    float y; asm("rcp.approx.f32 %0, %1;" : "=f"(y) : "f"(x)); return y;
}
__device__ __forceinline__ u64 ffma2(u64 a, u64 b, u64 c) {
    u64 d; asm("fma.rn.f32x2 %0, %1, %2, %3;" : "=l"(d) : "l"(a), "l"(b), "l"(c)); return d;
}
__device__ __forceinline__ u64 fadd2(u64 a, u64 b) {
    u64 d; asm("add.rn.f32x2 %0, %1, %2;" : "=l"(d) : "l"(a), "l"(b)); return d;
}
__device__ __forceinline__ u64 pack2(float lo, float hi) {
    u64 d; u32 l = __float_as_uint(lo), h = __float_as_uint(hi);
    asm("mov.b64 %0, {%1, %2};" : "=l"(d) : "r"(l), "r"(h)); return d;
}
__device__ __forceinline__ void unpack2(u64 v, float& lo, float& hi) {
    u32 l, h; asm("mov.b64 {%0, %1}, %2;" : "=r"(l), "=r"(h) : "l"(v));
    lo = __uint_as_float(l); hi = __uint_as_float(h);
}
union F4U { float4 f; u64 u[2]; };

__device__ __forceinline__ void bfsplit(float v, u16& hb, u16& lb) {
    __nv_bfloat16 h = __float2bfloat16(v);
    float rh = __bfloat162float(h);
    __nv_bfloat16 l = __float2bfloat16(v - rh);
    hb = *reinterpret_cast<u16*>(&h);
    lb = *reinterpret_cast<u16*>(&l);
}

// mma.sync m16n8k16 bf16 -> f32 accumulate in place
__device__ __forceinline__ void mma16816(float* c, const u32* a, const u32* b) {
    asm volatile(
        "mma.sync.aligned.m16n8k16.row.col.f32.bf16.bf16.f32 "
        "{%0,%1,%2,%3}, {%4,%5,%6,%7}, {%8,%9}, {%0,%1,%2,%3};"
        : "+f"(c[0]), "+f"(c[1]), "+f"(c[2]), "+f"(c[3])
        : "r"(a[0]), "r"(a[1]), "r"(a[2]), "r"(a[3]), "r"(b[0]), "r"(b[1]));
}

// ---------------------------------------------------------------------------
// HMMA GEMM: C[M x N] = A[M x K] @ B[K x N]; A as bf16 hi/lo row-major,
// B as transposed+split BT[N x K] K-major.
// Block tile 128x64, BK=32, 256 threads = 8 warps (4 M x 2 N), warp tile 32x32.
// 3 passes: Ah*Bh + Ah*Bl + Al*Bh.
// EPI: 0 fp32 C | 1 relu(acc+bias)->bf16 h/l | 2 resid+alpha*acc -> fp32 + h/l
//      3 resid+alpha*(acc+bias) -> fp32
// ---------------------------------------------------------------------------
#define GPAD 40   // smem row stride in bf16 (conflict-free fragment gathers)

template <int EPI>
__global__ void __launch_bounds__(256) mmagemm_k(
    const __nv_bfloat16* __restrict__ Ah, const __nv_bfloat16* __restrict__ Al, int lda,
    const __nv_bfloat16* __restrict__ BTh, const __nv_bfloat16* __restrict__ BTl,
    int K,
    float* __restrict__ C, int ldc,
    __nv_bfloat16* __restrict__ Chb, __nv_bfloat16* __restrict__ Clb, int ldcb,
    const float* __restrict__ bias,
    const float* __restrict__ resid, int ldr,
    const float* __restrict__ alphap)
{
    __shared__ __nv_bfloat16 sAh[128 * GPAD];
    __shared__ __nv_bfloat16 sAl[128 * GPAD];
    __shared__ __nv_bfloat16 sBh[64 * GPAD];
    __shared__ __nv_bfloat16 sBl[64 * GPAD];

    const int tid  = threadIdx.x;
    const int warp = tid >> 5;
    const int lane = tid & 31;
    const int grp  = lane >> 2;
    const int tig  = lane & 3;
    const int wm   = warp & 3;       // M warp coord (4)
    const int wn   = warp >> 2;      // N warp coord (2)
    const int row0 = blockIdx.y * 128;
    const int col0 = blockIdx.x * 64;

    float acc[2][4][4];
#pragma unroll
    for (int mt = 0; mt < 2; mt++)
#pragma unroll
        for (int nt = 0; nt < 4; nt++)
#pragma unroll
            for (int i = 0; i < 4; i++) acc[mt][nt][i] = 0.f;

    const int nchunks = K >> 5;
    for (int kc = 0; kc < nchunks; kc++) {
        const int k0 = kc * 32;
        // A tiles: 128 rows x 32 bf16 per half = 512 uint4, 2 per thread
#pragma unroll
        for (int i = 0; i < 2; i++) {
            int id = tid + i * 256;
            int row = id >> 2;
            int kk = (id & 3) * 8;
            const size_t go = (size_t)(row0 + row) * lda + k0 + kk;
            int dst = row * GPAD + kk;
            *(uint4*)&sAh[dst] = *(const uint4*)(Ah + go);
            *(uint4*)&sAl[dst] = *(const uint4*)(Al + go);
        }
        // B tiles: 64 rows x 32 bf16 per half = 256 uint4, 1 per thread
        {
            int n = tid >> 2;
            int kk = (tid & 3) * 8;
            const size_t go = (size_t)(col0 + n) * K + k0 + kk;
            int dst = n * GPAD + kk;
            *(uint4*)&sBh[dst] = *(const uint4*)(BTh + go);
            *(uint4*)&sBl[dst] = *(const uint4*)(BTl + go);
        }
        __syncthreads();

#pragma unroll
        for (int ks = 0; ks < 32; ks += 16) {
            u32 ah[2][4], al[2][4];
#pragma unroll
            for (int mt = 0; mt < 2; mt++) {
                int rm = wm * 32 + mt * 16;
                int b0 = (rm + grp) * GPAD + ks + tig * 2;
                int b8 = (rm + grp + 8) * GPAD + ks + tig * 2;
                ah[mt][0] = *(const u32*)&sAh[b0];
                ah[mt][1] = *(const u32*)&sAh[b8];
                ah[mt][2] = *(const u32*)&sAh[b0 + 8];
                ah[mt][3] = *(const u32*)&sAh[b8 + 8];
                al[mt][0] = *(const u32*)&sAl[b0];
                al[mt][1] = *(const u32*)&sAl[b8];
                al[mt][2] = *(const u32*)&sAl[b0 + 8];
                al[mt][3] = *(const u32*)&sAl[b8 + 8];
            }
            u32 bh[4][2], bl[4][2];
#pragma unroll
            for (int nt = 0; nt < 4; nt++) {
                int cn = wn * 32 + nt * 8;
                int b0 = (cn + grp) * GPAD + ks + tig * 2;
                bh[nt][0] = *(const u32*)&sBh[b0];
                bh[nt][1] = *(const u32*)&sBh[b0 + 8];
                bl[nt][0] = *(const u32*)&sBl[b0];
                bl[nt][1] = *(const u32*)&sBl[b0 + 8];
            }
#pragma unroll
            for (int mt = 0; mt < 2; mt++)
#pragma unroll
                for (int nt = 0; nt < 4; nt++) {
                    mma16816(acc[mt][nt], ah[mt], bh[nt]);
                    mma16816(acc[mt][nt], ah[mt], bl[nt]);
                    mma16816(acc[mt][nt], al[mt], bh[nt]);
                }
        }
        __syncthreads();
    }

    // ---------------- epilogue ----------------
    float alpha = 0.f;
    if (EPI == 2 || EPI == 3) alpha = __ldg(alphap);

#pragma unroll
    for (int mt = 0; mt < 2; mt++) {
#pragma unroll
        for (int rh = 0; rh < 2; rh++) {
            const int r = row0 + wm * 32 + mt * 16 + grp + rh * 8;
#pragma unroll
            for (int nt = 0; nt < 4; nt++) {
                const int c = col0 + wn * 32 + nt * 8 + tig * 2;
                float v0 = acc[mt][nt][rh * 2 + 0];
                float v1 = acc[mt][nt][rh * 2 + 1];
                if (EPI == 1 || EPI == 3) {
                    float2 bb = *(const float2*)&bias[c];
                    v0 += bb.x; v1 += bb.y;
                }
                if (EPI == 1) {
                    v0 = fmaxf(v0, 0.f); v1 = fmaxf(v1, 0.f);
                }
                if (EPI == 2 || EPI == 3) {
                    float2 rv = *(const float2*)&resid[(size_t)r * ldr + c];
                    v0 = fmaf(alpha, v0, rv.x);
                    v1 = fmaf(alpha, v1, rv.y);
                }
                if (EPI == 0 || EPI == 2 || EPI == 3)
                    *(float2*)&C[(size_t)r * ldc + c] = make_float2(v0, v1);
                if (EPI == 1 || EPI == 2) {
                    u16 h0, l0, h1, l1;
                    bfsplit(v0, h0, l0);
                    bfsplit(v1, h1, l1);
                    *(u32*)&Chb[(size_t)r * ldcb + c] = (u32)h0 | ((u32)h1 << 16);
                    *(u32*)&Clb[(size_t)r * ldcb + c] = (u32)l0 | ((u32)l1 << 16);
                }
            }
        }
    }
}

// ---------------------------------------------------------------------------
// Prep kernels
// ---------------------------------------------------------------------------
__global__ void __launch_bounds__(256) split_x_k(
    const float* __restrict__ x, __nv_bfloat16* __restrict__ xh,
    __nv_bfloat16* __restrict__ xl, int n4)
{
    int i = blockIdx.x * 256 + threadIdx.x;
    if (i >= n4) return;
    float4 vv = ((const float4*)x)[i];
    float a[4] = { vv.x, vv.y, vv.z, vv.w };
    u16 hb[4], lb[4];
#pragma unroll
    for (int j = 0; j < 4; j++) bfsplit(a[j], hb[j], lb[j]);
    ((uint2*)xh)[i] = make_uint2((u32)hb[0] | ((u32)hb[1] << 16), (u32)hb[2] | ((u32)hb[3] << 16));
    ((uint2*)xl)[i] = make_uint2((u32)lb[0] | ((u32)lb[1] << 16), (u32)lb[2] | ((u32)lb[3] << 16));
}

// WT[(rowoff+n)*ldo + k] = split(W[k*N + n])
__global__ void __launch_bounds__(256) wsplit_k(
    const float* __restrict__ W, int K, int N,
    __nv_bfloat16* __restrict__ Th, __nv_bfloat16* __restrict__ Tl,
    int ldo, int rowoff)
{
    int i = blockIdx.x * 256 + threadIdx.x;
    if (i >= N * K) return;
    int n = i / K, k = i - n * K;
    float vf = W[(size_t)k * N + n];
    u16 hb, lb;
    bfsplit(vf, hb, lb);
    Th[(size_t)(rowoff + n) * ldo + k] = *reinterpret_cast<__nv_bfloat16*>(&hb);
    Tl[(size_t)(rowoff + n) * ldo + k] = *reinterpret_cast<__nv_bfloat16*>(&lb);
}

// ---------------------------------------------------------------------------
// Fused attention (unchanged from round 3)
// ---------------------------------------------------------------------------
__global__ void __launch_bounds__(128) attn_k(
    const float* __restrict__ qkv, const float* __restrict__ e,
    float* __restrict__ attp, float* __restrict__ lp)
{
    __shared__ float  es[QTILE][33];
    __shared__ float4 kvs[KCHUNK][8];

    const int qt = blockIdx.x;
    const int h  = blockIdx.y;
    const int bz = blockIdx.z;
    const int b     = bz >> 2;
    const int split = bz & 3;
    const int tid = threadIdx.x;
    const int na = qt * QTILE + tid;
    const int nb = na + 128;

    u64 q2a[8], q2b[8];
    {
        const float4* qpa = (const float4*)(qkv + ((size_t)(b * SEQ + na)) * 384 + h * DH);
        const float4* qpb = (const float4*)(qkv + ((size_t)(b * SEQ + nb)) * 384 + h * DH);
#pragma unroll
        for (int i = 0; i < 4; i++) {
            F4U t; t.f = qpa[i]; q2a[2 * i] = t.u[0]; q2a[2 * i + 1] = t.u[1];
            F4U s; s.f = qpb[i]; q2b[2 * i] = s.u[0]; q2b[2 * i + 1] = s.u[1];
        }
    }

    u64 acca[8], accb[8];
#pragma unroll
    for (int i = 0; i < 8; i++) { acca[i] = 0ull; accb[i] = 0ull; }
    float la = 0.f, lb = 0.f;

    const int kstart = split * (SEQ / NSPLIT);

    for (int jc = 0; jc < (SEQ / NSPLIT) / KCHUNK; jc++) {
        const int k0 = kstart + jc * KCHUNK;
        __syncthreads();
#pragma unroll
        for (int i = 0; i < 2; i++) {
            int id = tid + i * 128;
            int key = id >> 3;
            int p = id & 7;
            const size_t base = ((size_t)(b * SEQ + k0 + key)) * 384 + 128 + h * DH
                              + (p & 3) * 4 + (p >> 2) * 128;
            kvs[key][p] = *(const float4*)(qkv + base);
        }
#pragma unroll
        for (int i = 0; i < 16; i++) {
            int fid = tid + i * 128;
            int k4 = fid & 7;
            int q  = fid >> 3;
            float4 vv = *(const float4*)&e[((size_t)(b * SEQ + qt * QTILE + q)) * SEQ + k0 + k4 * 4];
            es[q][k4 * 4 + 0] = vv.x; es[q][k4 * 4 + 1] = vv.y;
            es[q][k4 * 4 + 2] = vv.z; es[q][k4 * 4 + 3] = vv.w;
        }
        __syncthreads();

#pragma unroll 4
        for (int m = 0; m < KCHUNK; m++) {
            F4U kk0, kk1, kk2, kk3;
            kk0.f = kvs[m][0]; kk1.f = kvs[m][1]; kk2.f = kvs[m][2]; kk3.f = kvs[m][3];
            u64 ca0 = ffma2(q2a[0], kk0.u[0], 0ull);
            u64 cb0 = ffma2(q2b[0], kk0.u[0], 0ull);
            u64 ca1 = ffma2(q2a[2], kk1.u[0], 0ull);
            u64 cb1 = ffma2(q2b[2], kk1.u[0], 0ull);
            u64 ca2 = ffma2(q2a[4], kk2.u[0], 0ull);
            u64 cb2 = ffma2(q2b[4], kk2.u[0], 0ull);
            u64 ca3 = ffma2(q2a[6], kk3.u[0], 0ull);
            u64 cb3 = ffma2(q2b[6], kk3.u[0], 0ull);
            ca0 = ffma2(q2a[1], kk0.u[1], ca0);
            cb0 = ffma2(q2b[1], kk0.u[1], cb0);
            ca1 = ffma2(q2a[3], kk1.u[1], ca1);
            cb1 = ffma2(q2b[3], kk1.u[1], cb1);
            ca2 = ffma2(q2a[5], kk2.u[1], ca2);
            cb2 = ffma2(q2b[5], kk2.u[1], cb2);
            ca3 = ffma2(q2a[7], kk3.u[1], ca3);
            cb3 = ffma2(q2b[7], kk3.u[1], cb3);
            u64 sa = fadd2(fadd2(ca0, ca1), fadd2(ca2, ca3));
            u64 sb = fadd2(fadd2(cb0, cb1), fadd2(cb2, cb3));
            float sal, sah, sbl, sbh;
            unpack2(sa, sal, sah);
            unpack2(sb, sbl, sbh);
            float dota = sal + sah;
            float dotb = sbl + sbh;

            float eva = es[tid][m];
            float evb = es[tid + 128][m];
            float ssa = fmaf(dota, 0.25f, eva);
            float ssb = fmaf(dotb, 0.25f, evb);
            float ta = ex2f(2.8853901f * ssa);
            float tb = ex2f(2.8853901f * ssb);
            float ua = rcpf(ta + 1.0f);
            float ub = rcpf(tb + 1.0f);
            float wa = ex2f(-28.8539008f * ua);
            float wb = ex2f(-28.8539008f * ub);
            la += wa; lb += wb;

            u64 wpa = pack2(wa, wa);
            u64 wpb = pack2(wb, wb);
            F4U vv0, vv1, vv2, vv3;
            vv0.f = kvs[m][4]; vv1.f = kvs[m][5]; vv2.f = kvs[m][6]; vv3.f = kvs[m][7];
            acca[0] = ffma2(wpa, vv0.u[0], acca[0]);
            accb[0] = ffma2(wpb, vv0.u[0], accb[0]);
            acca[1] = ffma2(wpa, vv0.u[1], acca[1]);
            accb[1] = ffma2(wpb, vv0.u[1], accb[1]);
            acca[2] = ffma2(wpa, vv1.u[0], acca[2]);
            accb[2] = ffma2(wpb, vv1.u[0], accb[2]);
            acca[3] = ffma2(wpa, vv1.u[1], acca[3]);
            accb[3] = ffma2(wpb, vv1.u[1], accb[3]);
            acca[4] = ffma2(wpa, vv2.u[0], acca[4]);
            accb[4] = ffma2(wpb, vv2.u[0], accb[4]);
            acca[5] = ffma2(wpa, vv2.u[1], acca[5]);
            accb[5] = ffma2(wpb, vv2.u[1], accb[5]);
            acca[6] = ffma2(wpa, vv3.u[0], acca[6]);
            accb[6] = ffma2(wpb, vv3.u[0], accb[6]);
            acca[7] = ffma2(wpa, vv3.u[1], acca[7]);
            accb[7] = ffma2(wpb, vv3.u[1], accb[7]);
        }
    }

    float* opa = attp + ((size_t)split * MROWS + b * SEQ + na) * DIM + h * DH;
    float* opb = attp + ((size_t)split * MROWS + b * SEQ + nb) * DIM + h * DH;
#pragma unroll
    for (int i = 0; i < 4; i++) {
        F4U oa; oa.u[0] = acca[2 * i]; oa.u[1] = acca[2 * i + 1];
        *(float4*)(opa + 4 * i) = oa.f;
        F4U ob; ob.u[0] = accb[2 * i]; ob.u[1] = accb[2 * i + 1];
        *(float4*)(opb + 4 * i) = ob.f;
    }
    lp[((size_t)split * MROWS + b * SEQ + na) * HEADS + h] = la;
    lp[((size_t)split * MROWS + b * SEQ + nb) * HEADS + h] = lb;
}

// ---------------------------------------------------------------------------
// Combine split partials -> normalized att, written as bf16 hi/lo splits
// ---------------------------------------------------------------------------
__global__ void __launch_bounds__(256) combine_k(
    const float* __restrict__ attp, const float* __restrict__ lp,
    __nv_bfloat16* __restrict__ ath, __nv_bfloat16* __restrict__ atl)
{
    int idx = blockIdx.x * 256 + threadIdx.x;
    int row = idx >> 5;
    int c4  = idx & 31;
    int h   = c4 >> 2;
    float4 s = make_float4(0.f, 0.f, 0.f, 0.f);
    float l = 0.f;
#pragma unroll
    for (int sp = 0; sp < NSPLIT; sp++) {
        float4 vv = *(const float4*)&attp[((size_t)sp * MROWS + row) * DIM + c4 * 4];
        s.x += vv.x; s.y += vv.y; s.z += vv.z; s.w += vv.w;
        l += lp[((size_t)sp * MROWS + row) * HEADS + h];
    }
    float inv = 1.0f / l;
    float a[4] = { s.x * inv, s.y * inv, s.z * inv, s.w * inv };
    u16 hb[4], lbt[4];
#pragma unroll
    for (int j = 0; j < 4; j++) bfsplit(a[j], hb[j], lbt[j]);
    ((uint2*)ath)[idx] = make_uint2((u32)hb[0] | ((u32)hb[1] << 16),
                                    (u32)hb[2] | ((u32)hb[3] << 16));
    ((uint2*)atl)[idx] = make_uint2((u32)lbt[0] | ((u32)lbt[1] << 16),
                                    (u32)lbt[2] | ((u32)lbt[3] << 16));
}

// ---------------------------------------------------------------------------
// Launch
// ---------------------------------------------------------------------------
extern "C" void kernel_launch(void* const* d_in, const int* in_sizes, int n_in,
                              void* d_out, int out_size)
{
    const float* x  = (const float*)d_in[0];
    const float* e  = (const float*)d_in[1];
    const float* Wq = (const float*)d_in[2];
    const float* Wk = (const float*)d_in[3];
    const float* Wv = (const float*)d_in[4];
    const float* Wo = (const float*)d_in[5];
    const float* W1 = (const float*)d_in[6];
    const float* b1 = (const float*)d_in[7];
    const float* W2 = (const float*)d_in[8];
    const float* b2 = (const float*)d_in[9];
    const float* alpha1 = (const float*)d_in[10];
    const float* alpha2 = (const float*)d_in[11];
    float* out = (float*)d_out;

    float *qkv, *attp, *lpv, *x1;
    __nv_bfloat16 *xh, *xl, *ath, *atl, *x1h, *x1l, *ffh, *ffl;
    __nv_bfloat16 *WqkvTh, *WqkvTl, *WoTh, *WoTl, *W1Th, *W1Tl, *W2Th, *W2Tl;
    cudaGetSymbolAddress((void**)&qkv,  g_qkv);
    cudaGetSymbolAddress((void**)&attp, g_attp);
    cudaGetSymbolAddress((void**)&lpv,  g_lp);
    cudaGetSymbolAddress((void**)&x1,   g_x1);
    cudaGetSymbolAddress((void**)&xh,   g_xh);
    cudaGetSymbolAddress((void**)&xl,   g_xl);
    cudaGetSymbolAddress((void**)&ath,  g_ath);
    cudaGetSymbolAddress((void**)&atl,  g_atl);
    cudaGetSymbolAddress((void**)&x1h,  g_x1h);
    cudaGetSymbolAddress((void**)&x1l,  g_x1l);
    cudaGetSymbolAddress((void**)&ffh,  g_ffh);
    cudaGetSymbolAddress((void**)&ffl,  g_ffl);
    cudaGetSymbolAddress((void**)&WqkvTh, g_WqkvTh);
    cudaGetSymbolAddress((void**)&WqkvTl, g_WqkvTl);
    cudaGetSymbolAddress((void**)&WoTh, g_WoTh);
    cudaGetSymbolAddress((void**)&WoTl, g_WoTl);
    cudaGetSymbolAddress((void**)&W1Th, g_W1Th);
    cudaGetSymbolAddress((void**)&W1Tl, g_W1Tl);
    cudaGetSymbolAddress((void**)&W2Th, g_W2Th);
    cudaGetSymbolAddress((void**)&W2Tl, g_W2Tl);

    // preps
    split_x_k<<<(MROWS * DIM / 4 + 255) / 256, 256>>>(x, xh, xl, MROWS * DIM / 4);
    wsplit_k<<<(DIM * DIM + 255) / 256, 256>>>(Wq, DIM, DIM, WqkvTh, WqkvTl, DIM, 0);
    wsplit_k<<<(DIM * DIM + 255) / 256, 256>>>(Wk, DIM, DIM, WqkvTh, WqkvTl, DIM, 128);
    wsplit_k<<<(DIM * DIM + 255) / 256, 256>>>(Wv, DIM, DIM, WqkvTh, WqkvTl, DIM, 256);
    wsplit_k<<<(DIM * DIM + 255) / 256, 256>>>(Wo, DIM, DIM, WoTh, WoTl, DIM, 0);
    wsplit_k<<<(DIM * FFDIM + 255) / 256, 256>>>(W1, DIM, FFDIM, W1Th, W1Tl, DIM, 0);
    wsplit_k<<<(FFDIM * DIM + 255) / 256, 256>>>(W2, FFDIM, DIM, W2Th, W2Tl, FFDIM, 0);

    // qkv = x @ [Wq|Wk|Wv]   (fp32 out, ldc=384)
    mmagemm_k<0><<<dim3(384 / 64, MROWS / 128), 256>>>(
        xh, xl, DIM, WqkvTh, WqkvTl, DIM,
        qkv, 384, nullptr, nullptr, 0, nullptr, nullptr, 0, nullptr);

    attn_k<<<dim3(SEQ / QTILE, HEADS, BATCH * NSPLIT), 128>>>(qkv, e, attp, lpv);
    combine_k<<<(MROWS * DIM / 4) / 256, 256>>>(attp, lpv, ath, atl);

    // x1 = x + a1*(att @ Wo)  (fp32 x1 + bf16 splits)
    mmagemm_k<2><<<dim3(DIM / 64, MROWS / 128), 256>>>(
        ath, atl, DIM, WoTh, WoTl, DIM,
        x1, DIM, x1h, x1l, DIM, nullptr, x, DIM, alpha1);

    // ff = relu(x1 @ W1 + b1)  (bf16 splits only)
    mmagemm_k<1><<<dim3(FFDIM / 64, MROWS / 128), 256>>>(
        x1h, x1l, DIM, W1Th, W1Tl, DIM,
        nullptr, 0, ffh, ffl, FFDIM, b1, nullptr, 0, nullptr);

    // out = x1 + a2*(ff @ W2 + b2)  (fp32 out)
    mmagemm_k<3><<<dim3(DIM / 64, MROWS / 128), 256>>>(
        ffh, ffl, FFDIM, W2Th, W2Tl, FFDIM,
        out, DIM, nullptr, nullptr, 0, b2, x1, DIM, alpha2);
}

// round 6
// speedup vs baseline: 1.8795x; 1.3410x over previous
#include <cuda_runtime.h>
#include <cuda_bf16.h>
#include <cstdint>

// Problem constants
#define BATCH 8
#define SEQ   1024
#define DIM   128
#define HEADS 8
#define DH    16
#define FFDIM 512
#define MROWS (BATCH*SEQ)   // 8192
#define NSPLIT 2            // attention key splits

typedef unsigned long long u64;
typedef unsigned int u32;
typedef unsigned short u16;

// ------------------------- scratch (static only) ---------------------------
__device__ __align__(16) float g_attp[NSPLIT * MROWS * DIM];
__device__ __align__(16) float g_lp  [NSPLIT * MROWS * HEADS];
__device__ __align__(16) float g_x1  [MROWS * DIM];
// bf16 hi/lo split operands
__device__ __align__(16) __nv_bfloat16 g_qkvh[MROWS * 384], g_qkvl[MROWS * 384];
__device__ __align__(16) __nv_bfloat16 g_xh [MROWS * DIM],  g_xl [MROWS * DIM];
__device__ __align__(16) __nv_bfloat16 g_ath[MROWS * DIM],  g_atl[MROWS * DIM];
__device__ __align__(16) __nv_bfloat16 g_x1h[MROWS * DIM],  g_x1l[MROWS * DIM];
__device__ __align__(16) __nv_bfloat16 g_ffh[MROWS * FFDIM],g_ffl[MROWS * FFDIM];
// transposed + split weights: [N x K] K-major
__device__ __align__(16) __nv_bfloat16 g_WqkvTh[384 * DIM], g_WqkvTl[384 * DIM];
__device__ __align__(16) __nv_bfloat16 g_WoTh [DIM * DIM],  g_WoTl [DIM * DIM];
__device__ __align__(16) __nv_bfloat16 g_W1Th [FFDIM * DIM],g_W1Tl [FFDIM * DIM];
__device__ __align__(16) __nv_bfloat16 g_W2Th [DIM * FFDIM],g_W2Tl [DIM * FFDIM];

// ------------------------------ helpers ------------------------------------
__device__ __forceinline__ float ex2f(float x) {
    float y; asm("ex2.approx.f32 %0, %1;" : "=f"(y) : "f"(x)); return y;
}
__device__ __forceinline__ float rcpf(float x) {
    float y; asm("rcp.approx.f32 %0, %1;" : "=f"(y) : "f"(x)); return y;
}
__device__ __forceinline__ void bfsplit(float v, u16& hb, u16& lb) {
    __nv_bfloat16 h = __float2bfloat16(v);
    float rh = __bfloat162float(h);
    __nv_bfloat16 l = __float2bfloat16(v - rh);
    hb = *reinterpret_cast<u16*>(&h);
    lb = *reinterpret_cast<u16*>(&l);
}
// pack (w0 -> low 16, w1 -> high 16) bf16 hi + residual lo
__device__ __forceinline__ void pack_split2(float w0, float w1, u32& hp, u32& lp2) {
    __nv_bfloat162 hh = __floats2bfloat162_rn(w0, w1);   // .x = w0 (low)
    float2 back = __bfloat1622float2(hh);
    __nv_bfloat162 ll = __floats2bfloat162_rn(w0 - back.x, w1 - back.y);
    hp  = *reinterpret_cast<u32*>(&hh);
    lp2 = *reinterpret_cast<u32*>(&ll);
}
// w = exp(10*tanh(dot/4 + ev) - 10), fixed-max softmax weight
__device__ __forceinline__ float expw(float dot, float ev) {
    float t = ex2f(fmaf(dot, 0.72134752f, ev * 2.8853901f));   // exp(2s)
    float u = rcpf(t + 1.0f);
    return ex2f(-28.8539008f * u);                              // exp(-20/(t+1))
}
// mma.sync m16n8k16 bf16 -> f32 accumulate in place
__device__ __forceinline__ void mma16816(float* c, const u32* a, const u32* b) {
    asm volatile(
        "mma.sync.aligned.m16n8k16.row.col.f32.bf16.bf16.f32 "
        "{%0,%1,%2,%3}, {%4,%5,%6,%7}, {%8,%9}, {%0,%1,%2,%3};"
        : "+f"(c[0]), "+f"(c[1]), "+f"(c[2]), "+f"(c[3])
        : "r"(a[0]), "r"(a[1]), "r"(a[2]), "r"(a[3]), "r"(b[0]), "r"(b[1]));
}

// ---------------------------------------------------------------------------
// HMMA GEMM (verified round 5): C = A @ B, A bf16 h/l row-major, BT[N x K].
// Block 128x64, BK=32, 8 warps, warp tile 32x32, 3 split passes.
// EPI: 0 fp32 | 1 relu(acc+bias)->bf16 h/l | 2 resid+alpha*acc -> fp32+h/l
//      3 resid+alpha*(acc+bias) -> fp32 | 4 plain bf16 h/l
// ---------------------------------------------------------------------------
#define GPAD 40

template <int EPI>
__global__ void __launch_bounds__(256) mmagemm_k(
    const __nv_bfloat16* __restrict__ Ah, const __nv_bfloat16* __restrict__ Al, int lda,
    const __nv_bfloat16* __restrict__ BTh, const __nv_bfloat16* __restrict__ BTl,
    int K,
    float* __restrict__ C, int ldc,
    __nv_bfloat16* __restrict__ Chb, __nv_bfloat16* __restrict__ Clb, int ldcb,
    const float* __restrict__ bias,
    const float* __restrict__ resid, int ldr,
    const float* __restrict__ alphap)
{
    __shared__ __nv_bfloat16 sAh[128 * GPAD];
    __shared__ __nv_bfloat16 sAl[128 * GPAD];
    __shared__ __nv_bfloat16 sBh[64 * GPAD];
    __shared__ __nv_bfloat16 sBl[64 * GPAD];

    const int tid  = threadIdx.x;
    const int warp = tid >> 5;
    const int lane = tid & 31;
    const int grp  = lane >> 2;
    const int tig  = lane & 3;
    const int wm   = warp & 3;
    const int wn   = warp >> 2;
    const int row0 = blockIdx.y * 128;
    const int col0 = blockIdx.x * 64;

    float acc[2][4][4];
#pragma unroll
    for (int mt = 0; mt < 2; mt++)
#pragma unroll
        for (int nt = 0; nt < 4; nt++)
#pragma unroll
            for (int i = 0; i < 4; i++) acc[mt][nt][i] = 0.f;

    const int nchunks = K >> 5;
    for (int kc = 0; kc < nchunks; kc++) {
        const int k0 = kc * 32;
#pragma unroll
        for (int i = 0; i < 2; i++) {
            int id = tid + i * 256;
            int row = id >> 2;
            int kk = (id & 3) * 8;
            const size_t go = (size_t)(row0 + row) * lda + k0 + kk;
            int dst = row * GPAD + kk;
            *(uint4*)&sAh[dst] = *(const uint4*)(Ah + go);
            *(uint4*)&sAl[dst] = *(const uint4*)(Al + go);
        }
        {
            int n = tid >> 2;
            int kk = (tid & 3) * 8;
            const size_t go = (size_t)(col0 + n) * K + k0 + kk;
            int dst = n * GPAD + kk;
            *(uint4*)&sBh[dst] = *(const uint4*)(BTh + go);
            *(uint4*)&sBl[dst] = *(const uint4*)(BTl + go);
        }
        __syncthreads();

#pragma unroll
        for (int ks = 0; ks < 32; ks += 16) {
            u32 ah[2][4], al[2][4];
#pragma unroll
            for (int mt = 0; mt < 2; mt++) {
                int rm = wm * 32 + mt * 16;
                int b0 = (rm + grp) * GPAD + ks + tig * 2;
                int b8 = (rm + grp + 8) * GPAD + ks + tig * 2;
                ah[mt][0] = *(const u32*)&sAh[b0];
                ah[mt][1] = *(const u32*)&sAh[b8];
                ah[mt][2] = *(const u32*)&sAh[b0 + 8];
                ah[mt][3] = *(const u32*)&sAh[b8 + 8];
                al[mt][0] = *(const u32*)&sAl[b0];
                al[mt][1] = *(const u32*)&sAl[b8];
                al[mt][2] = *(const u32*)&sAl[b0 + 8];
                al[mt][3] = *(const u32*)&sAl[b8 + 8];
            }
            u32 bh[4][2], bl[4][2];
#pragma unroll
            for (int nt = 0; nt < 4; nt++) {
                int cn = wn * 32 + nt * 8;
                int b0 = (cn + grp) * GPAD + ks + tig * 2;
                bh[nt][0] = *(const u32*)&sBh[b0];
                bh[nt][1] = *(const u32*)&sBh[b0 + 8];
                bl[nt][0] = *(const u32*)&sBl[b0];
                bl[nt][1] = *(const u32*)&sBl[b0 + 8];
            }
#pragma unroll
            for (int mt = 0; mt < 2; mt++)
#pragma unroll
                for (int nt = 0; nt < 4; nt++) {
                    mma16816(acc[mt][nt], ah[mt], bh[nt]);
                    mma16816(acc[mt][nt], ah[mt], bl[nt]);
                    mma16816(acc[mt][nt], al[mt], bh[nt]);
                }
        }
        __syncthreads();
    }

    float alpha = 0.f;
    if (EPI == 2 || EPI == 3) alpha = __ldg(alphap);

#pragma unroll
    for (int mt = 0; mt < 2; mt++) {
#pragma unroll
        for (int rh = 0; rh < 2; rh++) {
            const int r = row0 + wm * 32 + mt * 16 + grp + rh * 8;
#pragma unroll
            for (int nt = 0; nt < 4; nt++) {
                const int c = col0 + wn * 32 + nt * 8 + tig * 2;
                float v0 = acc[mt][nt][rh * 2 + 0];
                float v1 = acc[mt][nt][rh * 2 + 1];
                if (EPI == 1 || EPI == 3) {
                    float2 bb = *(const float2*)&bias[c];
                    v0 += bb.x; v1 += bb.y;
                }
                if (EPI == 1) {
                    v0 = fmaxf(v0, 0.f); v1 = fmaxf(v1, 0.f);
                }
                if (EPI == 2 || EPI == 3) {
                    float2 rv = *(const float2*)&resid[(size_t)r * ldr + c];
                    v0 = fmaf(alpha, v0, rv.x);
                    v1 = fmaf(alpha, v1, rv.y);
                }
                if (EPI == 0 || EPI == 2 || EPI == 3)
                    *(float2*)&C[(size_t)r * ldc + c] = make_float2(v0, v1);
                if (EPI == 1 || EPI == 2 || EPI == 4) {
                    u16 h0, l0, h1, l1;
                    bfsplit(v0, h0, l0);
                    bfsplit(v1, h1, l1);
                    *(u32*)&Chb[(size_t)r * ldcb + c] = (u32)h0 | ((u32)h1 << 16);
                    *(u32*)&Clb[(size_t)r * ldcb + c] = (u32)l0 | ((u32)l1 << 16);
                }
            }
        }
    }
}

// ---------------------------------------------------------------------------
// Prep kernels
// ---------------------------------------------------------------------------
__global__ void __launch_bounds__(256) split_x_k(
    const float* __restrict__ x, __nv_bfloat16* __restrict__ xh,
    __nv_bfloat16* __restrict__ xl, int n4)
{
    int i = blockIdx.x * 256 + threadIdx.x;
    if (i >= n4) return;
    float4 vv = ((const float4*)x)[i];
    float a[4] = { vv.x, vv.y, vv.z, vv.w };
    u16 hb[4], lb[4];
#pragma unroll
    for (int j = 0; j < 4; j++) bfsplit(a[j], hb[j], lb[j]);
    ((uint2*)xh)[i] = make_uint2((u32)hb[0] | ((u32)hb[1] << 16), (u32)hb[2] | ((u32)hb[3] << 16));
    ((uint2*)xl)[i] = make_uint2((u32)lb[0] | ((u32)lb[1] << 16), (u32)lb[2] | ((u32)lb[3] << 16));
}

__global__ void __launch_bounds__(256) wsplit_k(
    const float* __restrict__ W, int K, int N,
    __nv_bfloat16* __restrict__ Th, __nv_bfloat16* __restrict__ Tl,
    int ldo, int rowoff)
{
    int i = blockIdx.x * 256 + threadIdx.x;
    if (i >= N * K) return;
    int n = i / K, k = i - n * K;
    float vf = W[(size_t)k * N + n];
    u16 hb, lb;
    bfsplit(vf, hb, lb);
    Th[(size_t)(rowoff + n) * ldo + k] = *reinterpret_cast<__nv_bfloat16*>(&hb);
    Tl[(size_t)(rowoff + n) * ldo + k] = *reinterpret_cast<__nv_bfloat16*>(&lb);
}

// ---------------------------------------------------------------------------
// Flash attention on HMMA. Block = 128 queries (8 warps x m16), one (b,h,split).
// K chunk 64 staged [key][dh] (stride 24 bf16, conflict-free); V staged
// transposed [dh][key] (stride 72 bf16). Fixed-max softmax in fragments.
// S = Q Kt (3-pass split), P split in regs, O += P V (3-pass split).
// ---------------------------------------------------------------------------
#define KSTR 24
#define VSTR 72

__global__ void __launch_bounds__(256) attn_mma_k(
    const __nv_bfloat16* __restrict__ qkvh, const __nv_bfloat16* __restrict__ qkvl,
    const float* __restrict__ e,
    float* __restrict__ attp, float* __restrict__ lp)
{
    __shared__ __nv_bfloat16 sKh[64 * KSTR], sKl[64 * KSTR];
    __shared__ __nv_bfloat16 sVh[16 * VSTR], sVl[16 * VSTR];

    const int qt = blockIdx.x;            // 0..7
    const int h  = blockIdx.y;
    const int bz = blockIdx.z;
    const int b = bz >> 1, split = bz & 1;
    const int tid = threadIdx.x;
    const int w = tid >> 5, lane = tid & 31;
    const int grp = lane >> 2, tig = lane & 3;

    const int qrow = qt * 128 + w * 16 + grp;     // local query row (and +8)
    const size_t grow = (size_t)b * SEQ + qrow;

    // Q fragments (m16 x k16), hi and lo
    u32 qfh[4], qfl[4];
    {
        const size_t b0 = grow * 384 + h * DH;
        const size_t b8 = (grow + 8) * 384 + h * DH;
        qfh[0] = *(const u32*)&qkvh[b0 + tig * 2];
        qfh[1] = *(const u32*)&qkvh[b8 + tig * 2];
        qfh[2] = *(const u32*)&qkvh[b0 + tig * 2 + 8];
        qfh[3] = *(const u32*)&qkvh[b8 + tig * 2 + 8];
        qfl[0] = *(const u32*)&qkvl[b0 + tig * 2];
        qfl[1] = *(const u32*)&qkvl[b8 + tig * 2];
        qfl[2] = *(const u32*)&qkvl[b0 + tig * 2 + 8];
        qfl[3] = *(const u32*)&qkvl[b8 + tig * 2 + 8];
    }

    float o0[4] = {0.f, 0.f, 0.f, 0.f};
    float o1[4] = {0.f, 0.f, 0.f, 0.f};
    float la = 0.f, lb = 0.f;

    const float* erow0 = e + grow * SEQ;
    const float* erow8 = erow0 + (size_t)8 * SEQ;
    const int kstart = split * (SEQ / NSPLIT);

    // staging ids (constant over chunks)
    const int skey = tid & 63;
    const int ssel = (tid >> 6) & 1;
    const int shl  = tid >> 7;
    const __nv_bfloat16* ssrc = shl ? qkvl : qkvh;
    __nv_bfloat16* kdst = shl ? sKl : sKh;
    __nv_bfloat16* vdst = shl ? sVl : sVh;

    for (int jc = 0; jc < (SEQ / NSPLIT) / 64; jc++) {
        const int k0 = kstart + jc * 64;
        __syncthreads();
        // stage K [key][dh]
        {
            const size_t g = ((size_t)b * SEQ + k0 + skey) * 384 + 128 + h * DH + ssel * 8;
            *(uint4*)&kdst[skey * KSTR + ssel * 8] = *(const uint4*)&ssrc[g];
        }
        // stage V transposed [dh][key]
        {
            const size_t g = ((size_t)b * SEQ + k0 + skey) * 384 + 256 + h * DH + ssel * 8;
            uint4 v4 = *(const uint4*)&ssrc[g];
            const __nv_bfloat16* vv = (const __nv_bfloat16*)&v4;
#pragma unroll
            for (int j = 0; j < 8; j++) vdst[(ssel * 8 + j) * VSTR + skey] = vv[j];
        }
        __syncthreads();

        // ---- QK + softmax, 8 n8 tiles ----
        u32 ph0[8], ph8[8], pl0[8], pl8[8];
#pragma unroll
        for (int nt = 0; nt < 8; nt++) {
            float c[4] = {0.f, 0.f, 0.f, 0.f};
            const int kr = (nt * 8 + grp) * KSTR + tig * 2;
            u32 bh[2], bl[2];
            bh[0] = *(const u32*)&sKh[kr];
            bh[1] = *(const u32*)&sKh[kr + 8];
            bl[0] = *(const u32*)&sKl[kr];
            bl[1] = *(const u32*)&sKl[kr + 8];
            mma16816(c, qfh, bh);
            mma16816(c, qfh, bl);
            mma16816(c, qfl, bh);

            const int col = k0 + nt * 8 + tig * 2;
            float2 e0 = *(const float2*)&erow0[col];
            float2 e8 = *(const float2*)&erow8[col];
            float w00 = expw(c[0], e0.x);
            float w01 = expw(c[1], e0.y);
            float w10 = expw(c[2], e8.x);
            float w11 = expw(c[3], e8.y);
            la += w00 + w01;
            lb += w10 + w11;
            pack_split2(w00, w01, ph0[nt], pl0[nt]);
            pack_split2(w10, w11, ph8[nt], pl8[nt]);
        }

        // ---- AV: O += P V, 4 k16 chunks ----
#pragma unroll
        for (int kc = 0; kc < 4; kc++) {
            u32 ah[4] = { ph0[2 * kc], ph8[2 * kc], ph0[2 * kc + 1], ph8[2 * kc + 1] };
            u32 al[4] = { pl0[2 * kc], pl8[2 * kc], pl0[2 * kc + 1], pl8[2 * kc + 1] };
            const int kk = kc * 16 + tig * 2;
            u32 b0h[2], b1h[2], b0l[2], b1l[2];
            b0h[0] = *(const u32*)&sVh[grp * VSTR + kk];
            b0h[1] = *(const u32*)&sVh[grp * VSTR + kk + 8];
            b1h[0] = *(const u32*)&sVh[(8 + grp) * VSTR + kk];
            b1h[1] = *(const u32*)&sVh[(8 + grp) * VSTR + kk + 8];
            b0l[0] = *(const u32*)&sVl[grp * VSTR + kk];
            b0l[1] = *(const u32*)&sVl[grp * VSTR + kk + 8];
            b1l[0] = *(const u32*)&sVl[(8 + grp) * VSTR + kk];
            b1l[1] = *(const u32*)&sVl[(8 + grp) * VSTR + kk + 8];
            mma16816(o0, ah, b0h);
            mma16816(o1, ah, b1h);
            mma16816(o0, al, b0h);
            mma16816(o1, al, b1h);
            mma16816(o0, ah, b0l);
            mma16816(o1, ah, b1l);
        }
    }

    // reduce denominators across the 4 tig lanes (same row)
    la += __shfl_xor_sync(0xffffffffu, la, 1);
    la += __shfl_xor_sync(0xffffffffu, la, 2);
    lb += __shfl_xor_sync(0xffffffffu, lb, 1);
    lb += __shfl_xor_sync(0xffffffffu, lb, 2);

    // store unnormalized partials
    float* opa = attp + ((size_t)split * MROWS + grow) * DIM + h * DH;
    float* opb = attp + ((size_t)split * MROWS + grow + 8) * DIM + h * DH;
    *(float2*)&opa[tig * 2]     = make_float2(o0[0], o0[1]);
    *(float2*)&opa[8 + tig * 2] = make_float2(o1[0], o1[1]);
    *(float2*)&opb[tig * 2]     = make_float2(o0[2], o0[3]);
    *(float2*)&opb[8 + tig * 2] = make_float2(o1[2], o1[3]);
    if (tig == 0) {
        lp[((size_t)split * MROWS + grow) * HEADS + h]     = la;
        lp[((size_t)split * MROWS + grow + 8) * HEADS + h] = lb;
    }
}

// ---------------------------------------------------------------------------
// Combine split partials -> normalized att as bf16 hi/lo
// ---------------------------------------------------------------------------
__global__ void __launch_bounds__(256) combine_k(
    const float* __restrict__ attp, const float* __restrict__ lp,
    __nv_bfloat16* __restrict__ ath, __nv_bfloat16* __restrict__ atl)
{
    int idx = blockIdx.x * 256 + threadIdx.x;
    int row = idx >> 5;
    int c4  = idx & 31;
    int h   = c4 >> 2;
    float4 s = make_float4(0.f, 0.f, 0.f, 0.f);
    float l = 0.f;
#pragma unroll
    for (int sp = 0; sp < NSPLIT; sp++) {
        float4 vv = *(const float4*)&attp[((size_t)sp * MROWS + row) * DIM + c4 * 4];
        s.x += vv.x; s.y += vv.y; s.z += vv.z; s.w += vv.w;
        l += lp[((size_t)sp * MROWS + row) * HEADS + h];
    }
    float inv = 1.0f / l;
    float a[4] = { s.x * inv, s.y * inv, s.z * inv, s.w * inv };
    u16 hb[4], lbt[4];
#pragma unroll
    for (int j = 0; j < 4; j++) bfsplit(a[j], hb[j], lbt[j]);
    ((uint2*)ath)[idx] = make_uint2((u32)hb[0] | ((u32)hb[1] << 16),
                                    (u32)hb[2] | ((u32)hb[3] << 16));
    ((uint2*)atl)[idx] = make_uint2((u32)lbt[0] | ((u32)lbt[1] << 16),
                                    (u32)lbt[2] | ((u32)lbt[3] << 16));
}

// ---------------------------------------------------------------------------
// Launch
// ---------------------------------------------------------------------------
extern "C" void kernel_launch(void* const* d_in, const int* in_sizes, int n_in,
                              void* d_out, int out_size)
{
    const float* x  = (const float*)d_in[0];
    const float* e  = (const float*)d_in[1];
    const float* Wq = (const float*)d_in[2];
    const float* Wk = (const float*)d_in[3];
    const float* Wv = (const float*)d_in[4];
    const float* Wo = (const float*)d_in[5];
    const float* W1 = (const float*)d_in[6];
    const float* b1 = (const float*)d_in[7];
    const float* W2 = (const float*)d_in[8];
    const float* b2 = (const float*)d_in[9];
    const float* alpha1 = (const float*)d_in[10];
    const float* alpha2 = (const float*)d_in[11];
    float* out = (float*)d_out;

    float *attp, *lpv, *x1;
    __nv_bfloat16 *qkvh, *qkvl, *xh, *xl, *ath, *atl, *x1h, *x1l, *ffh, *ffl;
    __nv_bfloat16 *WqkvTh, *WqkvTl, *WoTh, *WoTl, *W1Th, *W1Tl, *W2Th, *W2Tl;
    cudaGetSymbolAddress((void**)&attp, g_attp);
    cudaGetSymbolAddress((void**)&lpv,  g_lp);
    cudaGetSymbolAddress((void**)&x1,   g_x1);
    cudaGetSymbolAddress((void**)&qkvh, g_qkvh);
    cudaGetSymbolAddress((void**)&qkvl, g_qkvl);
    cudaGetSymbolAddress((void**)&xh,   g_xh);
    cudaGetSymbolAddress((void**)&xl,   g_xl);
    cudaGetSymbolAddress((void**)&ath,  g_ath);
    cudaGetSymbolAddress((void**)&atl,  g_atl);
    cudaGetSymbolAddress((void**)&x1h,  g_x1h);
    cudaGetSymbolAddress((void**)&x1l,  g_x1l);
    cudaGetSymbolAddress((void**)&ffh,  g_ffh);
    cudaGetSymbolAddress((void**)&ffl,  g_ffl);
    cudaGetSymbolAddress((void**)&WqkvTh, g_WqkvTh);
    cudaGetSymbolAddress((void**)&WqkvTl, g_WqkvTl);
    cudaGetSymbolAddress((void**)&WoTh, g_WoTh);
    cudaGetSymbolAddress((void**)&WoTl, g_WoTl);
    cudaGetSymbolAddress((void**)&W1Th, g_W1Th);
    cudaGetSymbolAddress((void**)&W1Tl, g_W1Tl);
    cudaGetSymbolAddress((void**)&W2Th, g_W2Th);
    cudaGetSymbolAddress((void**)&W2Tl, g_W2Tl);

    // preps
    split_x_k<<<(MROWS * DIM / 4 + 255) / 256, 256>>>(x, xh, xl, MROWS * DIM / 4);
    wsplit_k<<<(DIM * DIM + 255) / 256, 256>>>(Wq, DIM, DIM, WqkvTh, WqkvTl, DIM, 0);
    wsplit_k<<<(DIM * DIM + 255) / 256, 256>>>(Wk, DIM, DIM, WqkvTh, WqkvTl, DIM, 128);
    wsplit_k<<<(DIM * DIM + 255) / 256, 256>>>(Wv, DIM, DIM, WqkvTh, WqkvTl, DIM, 256);
    wsplit_k<<<(DIM * DIM + 255) / 256, 256>>>(Wo, DIM, DIM, WoTh, WoTl, DIM, 0);
    wsplit_k<<<(DIM * FFDIM + 255) / 256, 256>>>(W1, DIM, FFDIM, W1Th, W1Tl, DIM, 0);
    wsplit_k<<<(FFDIM * DIM + 255) / 256, 256>>>(W2, FFDIM, DIM, W2Th, W2Tl, FFDIM, 0);

    // qkv = x @ [Wq|Wk|Wv] -> bf16 hi/lo (ldcb=384)
    mmagemm_k<4><<<dim3(384 / 64, MROWS / 128), 256>>>(
        xh, xl, DIM, WqkvTh, WqkvTl, DIM,
        nullptr, 0, qkvh, qkvl, 384, nullptr, nullptr, 0, nullptr);

    // flash attention on tensor cores
    attn_mma_k<<<dim3(SEQ / 128, HEADS, BATCH * NSPLIT), 256>>>(qkvh, qkvl, e, attp, lpv);
    combine_k<<<(MROWS * DIM / 4) / 256, 256>>>(attp, lpv, ath, atl);

    // x1 = x + a1*(att @ Wo)
    mmagemm_k<2><<<dim3(DIM / 64, MROWS / 128), 256>>>(
        ath, atl, DIM, WoTh, WoTl, DIM,
        x1, DIM, x1h, x1l, DIM, nullptr, x, DIM, alpha1);

    // ff = relu(x1 @ W1 + b1)
    mmagemm_k<1><<<dim3(FFDIM / 64, MROWS / 128), 256>>>(
        x1h, x1l, DIM, W1Th, W1Tl, DIM,
        nullptr, 0, ffh, ffl, FFDIM, b1, nullptr, 0, nullptr);

    // out = x1 + a2*(ff @ W2 + b2)
    mmagemm_k<3><<<dim3(DIM / 64, MROWS / 128), 256>>>(
        ffh, ffl, FFDIM, W2Th, W2Tl, FFDIM,
        out, DIM, nullptr, nullptr, 0, b2, x1, DIM, alpha2);
}